// round 1
// baseline (speedup 1.0000x reference)
#include <cuda_runtime.h>

// Problem constants
#define BB   2
#define SS   1024
#define DD   1024
#define HH   16
#define HDIM 64
#define WIN  256
#define FF   4096
#define MR   (BB*SS)   // 2048 rows

// ---------------- scratch (device globals; no allocation allowed) ----------
__device__ float g_h  [MR*DD];
__device__ float g_q  [MR*DD];
__device__ float g_k  [MR*DD];
__device__ float g_v  [MR*DD];
__device__ float g_ao [MR*DD];
__device__ float g_x1 [MR*DD];
__device__ float g_h2 [MR*DD];
__device__ float g_gate[MR*FF];
__device__ float g_up  [MR*FF];

// ---------------- RMSNorm: one block per row, 256 threads, D=1024 ----------
__global__ void rmsnorm_kernel(const float* __restrict__ x,
                               const float* __restrict__ w,
                               float* __restrict__ out) {
    int row = blockIdx.x;
    int tid = threadIdx.x;
    const float4 xv = ((const float4*)(x + (size_t)row * DD))[tid];
    float ss = xv.x*xv.x + xv.y*xv.y + xv.z*xv.z + xv.w*xv.w;
    #pragma unroll
    for (int o = 16; o; o >>= 1) ss += __shfl_xor_sync(0xffffffffu, ss, o);
    __shared__ float red[8];
    if ((tid & 31) == 0) red[tid >> 5] = ss;
    __syncthreads();
    if (tid < 32) {
        float v = (tid < 8) ? red[tid] : 0.f;
        #pragma unroll
        for (int o = 4; o; o >>= 1) v += __shfl_xor_sync(0xffffffffu, v, o);
        if (tid == 0) red[0] = v;
    }
    __syncthreads();
    float inv = rsqrtf(red[0] * (1.0f / DD) + 1e-6f);
    float4 wv = ((const float4*)w)[tid];
    float4 o4;
    o4.x = xv.x * inv * wv.x; o4.y = xv.y * inv * wv.y;
    o4.z = xv.z * inv * wv.z; o4.w = xv.w * inv * wv.w;
    ((float4*)(out + (size_t)row * DD))[tid] = o4;
}

// ---------------- RoPE in-place on q and k (pair per thread) ---------------
__global__ void rope_kernel(float* __restrict__ q, float* __restrict__ k) {
    int t = blockIdx.x * blockDim.x + threadIdx.x;     // 2 * MR * 512 threads
    int total = MR * 512;
    float* p = (t < total) ? q : k;
    int u = (t < total) ? t : (t - total);
    int m  = u >> 9;          // row 0..2047
    int pr = u & 511;         // pair index
    int hh = pr >> 5;         // head
    int i  = pr & 31;         // freq index within head
    int s  = m & (SS - 1);    // position
    // inv_freq = 10000^{-i/32}
    float inv = expf(-(float)i * 0.28782313662425576f);   // ln(10000)/32
    float ang = (float)s * inv;
    float c = cosf(ang), sn = sinf(ang);
    size_t base = (size_t)m * DD + hh * HDIM + i;
    float x1 = p[base];
    float x2 = p[base + 32];
    p[base]      = x1 * c - x2 * sn;
    p[base + 32] = x2 * c + x1 * sn;
}

// ---------------- generic fp32 NT GEMM: C[M,N] = A[M,K] @ W[N,K]^T ---------
// 128x128 tile, BK=8, 256 threads, 8x8 microtile.
template<bool HAS_BIAS, bool HAS_RES, bool FUSE_SILU>
__global__ void __launch_bounds__(256)
gemm_nt(const float* __restrict__ A, const float* __restrict__ W,
        const float* __restrict__ bias, const float* __restrict__ res,
        const float* __restrict__ gate, float* __restrict__ C,
        int M, int N, int K) {
    __shared__ float As[8][128];
    __shared__ float Bs[8][128];
    int bm = blockIdx.y, bn = blockIdx.x;
    int tid = threadIdx.x;
    int ar = tid >> 1;            // 0..127
    int ac = (tid & 1) * 4;       // 0 or 4
    const float* Aptr = A + (size_t)(bm * 128 + ar) * K + ac;
    const float* Wptr = W + (size_t)(bn * 128 + ar) * K + ac;
    int tx = tid & 15, ty = tid >> 4;
    float acc[8][8];
    #pragma unroll
    for (int i = 0; i < 8; i++)
        #pragma unroll
        for (int j = 0; j < 8; j++) acc[i][j] = 0.f;

    for (int k0 = 0; k0 < K; k0 += 8) {
        float4 av = *(const float4*)(Aptr + k0);
        float4 wv = *(const float4*)(Wptr + k0);
        As[ac + 0][ar] = av.x; As[ac + 1][ar] = av.y;
        As[ac + 2][ar] = av.z; As[ac + 3][ar] = av.w;
        Bs[ac + 0][ar] = wv.x; Bs[ac + 1][ar] = wv.y;
        Bs[ac + 2][ar] = wv.z; Bs[ac + 3][ar] = wv.w;
        __syncthreads();
        #pragma unroll
        for (int kk = 0; kk < 8; kk++) {
            float a[8], b[8];
            *(float4*)(a)     = *(const float4*)&As[kk][ty * 8];
            *(float4*)(a + 4) = *(const float4*)&As[kk][ty * 8 + 4];
            *(float4*)(b)     = *(const float4*)&Bs[kk][tx * 8];
            *(float4*)(b + 4) = *(const float4*)&Bs[kk][tx * 8 + 4];
            #pragma unroll
            for (int i = 0; i < 8; i++)
                #pragma unroll
                for (int j = 0; j < 8; j++) acc[i][j] += a[i] * b[j];
        }
        __syncthreads();
    }

    int colb = bn * 128 + tx * 8;
    #pragma unroll
    for (int i = 0; i < 8; i++) {
        int row = bm * 128 + ty * 8 + i;
        size_t idx = (size_t)row * N + colb;
        float4 c0 = make_float4(acc[i][0], acc[i][1], acc[i][2], acc[i][3]);
        float4 c1 = make_float4(acc[i][4], acc[i][5], acc[i][6], acc[i][7]);
        if (HAS_BIAS) {
            float4 b0 = *(const float4*)(bias + colb);
            float4 b1 = *(const float4*)(bias + colb + 4);
            c0.x += b0.x; c0.y += b0.y; c0.z += b0.z; c0.w += b0.w;
            c1.x += b1.x; c1.y += b1.y; c1.z += b1.z; c1.w += b1.w;
        }
        if (HAS_RES) {
            float4 r0 = *(const float4*)(res + idx);
            float4 r1 = *(const float4*)(res + idx + 4);
            c0.x += r0.x; c0.y += r0.y; c0.z += r0.z; c0.w += r0.w;
            c1.x += r1.x; c1.y += r1.y; c1.z += r1.z; c1.w += r1.w;
        }
        if (FUSE_SILU) {
            float4 g0 = *(const float4*)(gate + idx);
            float4 g1 = *(const float4*)(gate + idx + 4);
            c0.x *= g0.x / (1.f + expf(-g0.x));
            c0.y *= g0.y / (1.f + expf(-g0.y));
            c0.z *= g0.z / (1.f + expf(-g0.z));
            c0.w *= g0.w / (1.f + expf(-g0.w));
            c1.x *= g1.x / (1.f + expf(-g1.x));
            c1.y *= g1.y / (1.f + expf(-g1.y));
            c1.z *= g1.z / (1.f + expf(-g1.z));
            c1.w *= g1.w / (1.f + expf(-g1.w));
        }
        *(float4*)(C + idx)     = c0;
        *(float4*)(C + idx + 4) = c1;
    }
}

// ---------------- sliding-window attention -------------------------------
// Block: 64 queries of one (b,h). Materializes probs to attn_out and computes
// P@V into g_ao. Dynamic smem: Qs[64][65] + KVs[64][65] + sc[64][321].
#define QS_STRIDE 65
#define SC_STRIDE 321
#define SC_OFF    (2 * 64 * QS_STRIDE)

__global__ void __launch_bounds__(256)
attn_kernel(const float* __restrict__ q, const float* __restrict__ k,
            const float* __restrict__ v, float* __restrict__ ao,
            float* __restrict__ attn_out) {
    extern __shared__ float sm[];
    float* Qs  = sm;                       // [d][qq] stride 65
    float* KVs = sm + 64 * QS_STRIDE;      // phase A: [d][kk]; phase D: [kk][d]
    float* sc  = sm + SC_OFF;              // [qq][slot] stride 321, 320 slots

    int q0 = blockIdx.x * 64;
    int bh = blockIdx.y;
    int b  = bh >> 4, h = bh & 15;
    int tid = threadIdx.x;
    int tx = tid & 15, ty = tid >> 4;
    const float scale = 0.125f;   // 1/sqrt(64)

    // load Q tile (d-major)
    for (int t = tid; t < 64 * 64; t += 256) {
        int qq = t >> 6, d = t & 63;
        Qs[d * QS_STRIDE + qq] = q[((size_t)(b * SS + q0 + qq)) * DD + h * HDIM + d];
    }

    // -------- Phase A: scores for 5 key chunks of 64 ----------------------
    for (int c = 0; c < 5; c++) {
        int jb = q0 - 256 + c * 64;
        for (int t = tid; t < 64 * 64; t += 256) {
            int kk = t >> 6, d = t & 63;
            int j = jb + kk;
            KVs[d * QS_STRIDE + kk] =
                (j >= 0) ? k[((size_t)(b * SS + j)) * DD + h * HDIM + d] : 0.f;
        }
        __syncthreads();
        float acc[4][4];
        #pragma unroll
        for (int i = 0; i < 4; i++)
            #pragma unroll
            for (int j = 0; j < 4; j++) acc[i][j] = 0.f;
        #pragma unroll 8
        for (int d = 0; d < 64; d++) {
            float a[4], bb[4];
            #pragma unroll
            for (int i = 0; i < 4; i++) a[i]  = Qs [d * QS_STRIDE + ty * 4 + i];
            #pragma unroll
            for (int j = 0; j < 4; j++) bb[j] = KVs[d * QS_STRIDE + tx * 4 + j];
            #pragma unroll
            for (int i = 0; i < 4; i++)
                #pragma unroll
                for (int j = 0; j < 4; j++) acc[i][j] += a[i] * bb[j];
        }
        #pragma unroll
        for (int i = 0; i < 4; i++) {
            int qi = q0 + ty * 4 + i;
            #pragma unroll
            for (int j = 0; j < 4; j++) {
                int jj = jb + tx * 4 + j;
                bool valid = (jj >= 0) && (jj <= qi) && (qi - jj < WIN);
                sc[(ty * 4 + i) * SC_STRIDE + c * 64 + tx * 4 + j] =
                    valid ? acc[i][j] * scale : -1e30f;
            }
        }
        __syncthreads();
    }

    // -------- Phase B: softmax per query row (4 threads / row) ------------
    {
        int qq = tid >> 2, g = tid & 3;
        float* row = sc + qq * SC_STRIDE;
        float mx = -1e30f;
        for (int s = g; s < 320; s += 4) mx = fmaxf(mx, row[s]);
        mx = fmaxf(mx, __shfl_xor_sync(0xffffffffu, mx, 1));
        mx = fmaxf(mx, __shfl_xor_sync(0xffffffffu, mx, 2));
        float sum = 0.f;
        for (int s = g; s < 320; s += 4) {
            float e = expf(row[s] - mx);
            row[s] = e;
            sum += e;
        }
        sum += __shfl_xor_sync(0xffffffffu, sum, 1);
        sum += __shfl_xor_sync(0xffffffffu, sum, 2);
        float inv = 1.f / sum;
        for (int s = g; s < 320; s += 4) row[s] *= inv;
    }
    __syncthreads();

    // -------- Phase C: write full attn rows (zeros + probs) ---------------
    for (int qq = 0; qq < 64; qq++) {
        int qi = q0 + qq;
        float* dst = attn_out + ((size_t)bh * SS + qi) * SS;
        const float* src = sc + qq * SC_STRIDE;
        float r[4];
        #pragma unroll
        for (int u = 0; u < 4; u++) {
            int j = tid * 4 + u;
            bool in = (j <= qi) && (qi - j < WIN);
            r[u] = in ? src[j - q0 + 256] : 0.f;
        }
        ((float4*)dst)[tid] = make_float4(r[0], r[1], r[2], r[3]);
    }

    // -------- Phase D: out = P @ V ----------------------------------------
    float oacc[4][4];
    #pragma unroll
    for (int i = 0; i < 4; i++)
        #pragma unroll
        for (int j = 0; j < 4; j++) oacc[i][j] = 0.f;

    for (int c = 0; c < 5; c++) {
        int jb = q0 - 256 + c * 64;
        __syncthreads();
        for (int t = tid; t < 64 * 64; t += 256) {
            int kk = t >> 6, d = t & 63;
            int j = jb + kk;
            KVs[kk * QS_STRIDE + d] =
                (j >= 0) ? v[((size_t)(b * SS + j)) * DD + h * HDIM + d] : 0.f;
        }
        __syncthreads();
        #pragma unroll 8
        for (int kk = 0; kk < 64; kk++) {
            float p[4], bv[4];
            #pragma unroll
            for (int i = 0; i < 4; i++)
                p[i] = sc[(ty * 4 + i) * SC_STRIDE + c * 64 + kk];
            #pragma unroll
            for (int j = 0; j < 4; j++)
                bv[j] = KVs[kk * QS_STRIDE + tx * 4 + j];
            #pragma unroll
            for (int i = 0; i < 4; i++)
                #pragma unroll
                for (int j = 0; j < 4; j++) oacc[i][j] += p[i] * bv[j];
        }
    }

    #pragma unroll
    for (int i = 0; i < 4; i++) {
        size_t base = ((size_t)(b * SS + q0 + ty * 4 + i)) * DD + h * HDIM + tx * 4;
        *(float4*)(ao + base) = make_float4(oacc[i][0], oacc[i][1], oacc[i][2], oacc[i][3]);
    }
}

// ---------------- launcher -------------------------------------------------
extern "C" void kernel_launch(void* const* d_in, const int* in_sizes, int n_in,
                              void* d_out, int out_size) {
    const float* x   = (const float*)d_in[0];
    const float* wq  = (const float*)d_in[1];
    const float* bq  = (const float*)d_in[2];
    const float* wk  = (const float*)d_in[3];
    const float* bk  = (const float*)d_in[4];
    const float* wv  = (const float*)d_in[5];
    const float* bv  = (const float*)d_in[6];
    const float* wo  = (const float*)d_in[7];
    const float* bo  = (const float*)d_in[8];
    const float* anw = (const float*)d_in[9];
    const float* fnw = (const float*)d_in[10];
    const float* gw  = (const float*)d_in[11];
    const float* uw  = (const float*)d_in[12];
    const float* dw  = (const float*)d_in[13];

    float* outx = (float*)d_out;                       // [B,S,D]
    float* outa = outx + (size_t)MR * DD;              // [B,H,S,S]

    float *p_h, *p_q, *p_k, *p_v, *p_ao, *p_x1, *p_h2, *p_gate, *p_up;
    cudaGetSymbolAddress((void**)&p_h,    g_h);
    cudaGetSymbolAddress((void**)&p_q,    g_q);
    cudaGetSymbolAddress((void**)&p_k,    g_k);
    cudaGetSymbolAddress((void**)&p_v,    g_v);
    cudaGetSymbolAddress((void**)&p_ao,   g_ao);
    cudaGetSymbolAddress((void**)&p_x1,   g_x1);
    cudaGetSymbolAddress((void**)&p_h2,   g_h2);
    cudaGetSymbolAddress((void**)&p_gate, g_gate);
    cudaGetSymbolAddress((void**)&p_up,   g_up);

    // attn smem
    const int attn_smem = (2 * 64 * QS_STRIDE + 64 * SC_STRIDE) * sizeof(float);
    cudaFuncSetAttribute(attn_kernel,
                         cudaFuncAttributeMaxDynamicSharedMemorySize, attn_smem);

    dim3 gD(DD / 128, MR / 128);   // (8,16)
    dim3 gF(FF / 128, MR / 128);   // (32,16)

    // 1) attn rmsnorm
    rmsnorm_kernel<<<MR, 256>>>(x, anw, p_h);
    // 2) QKV
    gemm_nt<true, false, false><<<gD, 256>>>(p_h, wq, bq, nullptr, nullptr, p_q, MR, DD, DD);
    gemm_nt<true, false, false><<<gD, 256>>>(p_h, wk, bk, nullptr, nullptr, p_k, MR, DD, DD);
    gemm_nt<true, false, false><<<gD, 256>>>(p_h, wv, bv, nullptr, nullptr, p_v, MR, DD, DD);
    // 3) RoPE (q and k in one launch)
    rope_kernel<<<(2 * MR * 512) / 256, 256>>>(p_q, p_k);
    // 4) attention (writes probs to outa, context to g_ao)
    attn_kernel<<<dim3(SS / 64, BB * HH), 256, attn_smem>>>(p_q, p_k, p_v, p_ao, outa);
    // 5) O proj + residual
    gemm_nt<true, true, false><<<gD, 256>>>(p_ao, wo, bo, x, nullptr, p_x1, MR, DD, DD);
    // 6) ffn rmsnorm
    rmsnorm_kernel<<<MR, 256>>>(p_x1, fnw, p_h2);
    // 7) gate
    gemm_nt<false, false, false><<<gF, 256>>>(p_h2, gw, nullptr, nullptr, nullptr, p_gate, MR, FF, DD);
    // 8) up with fused silu(gate)*up
    gemm_nt<false, false, true><<<gF, 256>>>(p_h2, uw, nullptr, nullptr, p_gate, p_up, MR, FF, DD);
    // 9) down + residual -> final x output
    gemm_nt<false, true, false><<<gD, 256>>>(p_up, dw, nullptr, p_x1, nullptr, outx, MR, DD, FF);
}

// round 2
// speedup vs baseline: 2.4935x; 2.4935x over previous
#include <cuda_runtime.h>
#include <cstdint>

// Problem constants
#define BB   2
#define SS   1024
#define DD   1024
#define HH   16
#define HDIM 64
#define WIN  256
#define FF   4096
#define MR   (BB*SS)   // 2048 rows

// ---------------- scratch (device globals; no allocation allowed) ----------
__device__ float g_h  [MR*DD];
__device__ float g_q  [MR*DD];
__device__ float g_k  [MR*DD];
__device__ float g_v  [MR*DD];
__device__ float g_ao [MR*DD];
__device__ float g_x1 [MR*DD];
__device__ float g_h2 [MR*DD];
__device__ float g_gate[MR*FF];
__device__ float g_up  [MR*FF];

// ---------------- RMSNorm: one block per row, 256 threads, D=1024 ----------
__global__ void rmsnorm_kernel(const float* __restrict__ x,
                               const float* __restrict__ w,
                               float* __restrict__ out) {
    int row = blockIdx.x;
    int tid = threadIdx.x;
    const float4 xv = ((const float4*)(x + (size_t)row * DD))[tid];
    float ss = xv.x*xv.x + xv.y*xv.y + xv.z*xv.z + xv.w*xv.w;
    #pragma unroll
    for (int o = 16; o; o >>= 1) ss += __shfl_xor_sync(0xffffffffu, ss, o);
    __shared__ float red[8];
    if ((tid & 31) == 0) red[tid >> 5] = ss;
    __syncthreads();
    if (tid < 32) {
        float v = (tid < 8) ? red[tid] : 0.f;
        #pragma unroll
        for (int o = 4; o; o >>= 1) v += __shfl_xor_sync(0xffffffffu, v, o);
        if (tid == 0) red[0] = v;
    }
    __syncthreads();
    float inv = rsqrtf(red[0] * (1.0f / DD) + 1e-6f);
    float4 wv = ((const float4*)w)[tid];
    float4 o4;
    o4.x = xv.x * inv * wv.x; o4.y = xv.y * inv * wv.y;
    o4.z = xv.z * inv * wv.z; o4.w = xv.w * inv * wv.w;
    ((float4*)(out + (size_t)row * DD))[tid] = o4;
}

// ---------------- RoPE in-place on q and k (pair per thread) ---------------
__global__ void rope_kernel(float* __restrict__ q, float* __restrict__ k) {
    int t = blockIdx.x * blockDim.x + threadIdx.x;     // 2 * MR * 512 threads
    int total = MR * 512;
    float* p = (t < total) ? q : k;
    int u = (t < total) ? t : (t - total);
    int m  = u >> 9;          // row 0..2047
    int pr = u & 511;         // pair index
    int hh = pr >> 5;         // head
    int i  = pr & 31;         // freq index within head
    int s  = m & (SS - 1);    // position
    float inv = expf(-(float)i * 0.28782313662425576f);   // ln(10000)/32
    float ang = (float)s * inv;
    float c = cosf(ang), sn = sinf(ang);
    size_t base = (size_t)m * DD + hh * HDIM + i;
    float x1 = p[base];
    float x2 = p[base + 32];
    p[base]      = x1 * c - x2 * sn;
    p[base + 32] = x2 * c + x1 * sn;
}

// ---------------- silu(gate) * up, in place into up ------------------------
__global__ void silu_mul_kernel(const float* __restrict__ g, float* __restrict__ u) {
    int i = blockIdx.x * blockDim.x + threadIdx.x;
    float4 gv = ((const float4*)g)[i];
    float4 uv = ((float4*)u)[i];
    uv.x *= gv.x / (1.f + expf(-gv.x));
    uv.y *= gv.y / (1.f + expf(-gv.y));
    uv.z *= gv.z / (1.f + expf(-gv.z));
    uv.w *= gv.w / (1.f + expf(-gv.w));
    ((float4*)u)[i] = uv;
}

// ---------------- tf32 tensor-core GEMM ------------------------------------
// C[M,N] = A[M,K] @ W[N,K]^T (+bias, +res). 128x128x16 tile, 256 threads,
// 8 warps (2x4), warp tile 64x32, mma.m16n8k8.tf32, cp.async double buffer.
// PRECISE: 3xTF32 split (hi/lo) for ~fp32 accuracy.

struct GemmArgs {
    const float* w[3];
    const float* b[3];
    float* c[3];
};

__device__ __forceinline__ void cp16(void* smem_dst, const void* gsrc) {
    uint32_t s = (uint32_t)__cvta_generic_to_shared(smem_dst);
    asm volatile("cp.async.cg.shared.global [%0], [%1], 16;\n" :: "r"(s), "l"(gsrc));
}
__device__ __forceinline__ uint32_t f2tf32(float x) {
    uint32_t u;
    asm("cvt.rna.tf32.f32 %0, %1;" : "=r"(u) : "f"(x));
    return u;
}
__device__ __forceinline__ void split_tf32(float x, uint32_t& hi, uint32_t& lo) {
    hi = f2tf32(x);
    float rem = x - __uint_as_float(hi);
    lo = f2tf32(rem);
}
__device__ __forceinline__ void mma8(float* d, const uint32_t* a, const uint32_t* b) {
    asm volatile(
        "mma.sync.aligned.m16n8k8.row.col.f32.tf32.tf32.f32 "
        "{%0,%1,%2,%3}, {%4,%5,%6,%7}, {%8,%9}, {%0,%1,%2,%3};\n"
        : "+f"(d[0]), "+f"(d[1]), "+f"(d[2]), "+f"(d[3])
        : "r"(a[0]), "r"(a[1]), "r"(a[2]), "r"(a[3]), "r"(b[0]), "r"(b[1]));
}

template<bool HAS_BIAS, bool HAS_RES, bool PRECISE>
__global__ void __launch_bounds__(256)
gemm_tf32(const float* __restrict__ A, GemmArgs args,
          const float* __restrict__ res, int M, int N, int K) {
    const float* __restrict__ W = args.w[blockIdx.z];
    const float* __restrict__ bias = args.b[blockIdx.z];
    float* __restrict__ C = args.c[blockIdx.z];

    __shared__ float As[2][128][20];   // [stage][m][k] pad to 20 (conflict-free frags)
    __shared__ float Bs[2][128][20];   // [stage][n][k]

    int bm = blockIdx.y, bn = blockIdx.x;
    int tid = threadIdx.x;
    int lane = tid & 31, warp = tid >> 5;
    int wm = (warp >> 2) * 64;         // warp row offset: 0 or 64
    int wn = (warp & 3) * 32;          // warp col offset: 0..96
    int r = lane >> 2, cq = lane & 3;

    float acc[4][4][4];
    #pragma unroll
    for (int i = 0; i < 4; i++)
        #pragma unroll
        for (int j = 0; j < 4; j++)
            #pragma unroll
            for (int t = 0; t < 4; t++) acc[i][j][t] = 0.f;

    const float* Abase = A + (size_t)(bm * 128) * K;
    const float* Wbase = W + (size_t)(bn * 128) * K;
    int tr  = tid >> 2;                // 0..63
    int tkc = (tid & 3) << 2;          // 0,4,8,12

    auto load_tile = [&](int st, int k0) {
        cp16(&As[st][tr][tkc],      Abase + (size_t)tr * K + k0 + tkc);
        cp16(&As[st][tr + 64][tkc], Abase + (size_t)(tr + 64) * K + k0 + tkc);
        cp16(&Bs[st][tr][tkc],      Wbase + (size_t)tr * K + k0 + tkc);
        cp16(&Bs[st][tr + 64][tkc], Wbase + (size_t)(tr + 64) * K + k0 + tkc);
    };

    int nk = K >> 4;
    load_tile(0, 0);
    asm volatile("cp.async.commit_group;\n" ::);

    int buf = 0;
    for (int kt = 0; kt < nk; kt++) {
        asm volatile("cp.async.wait_group 0;\n" ::);
        __syncthreads();
        if (kt + 1 < nk) {
            load_tile(buf ^ 1, (kt + 1) * 16);
            asm volatile("cp.async.commit_group;\n" ::);
        }

        #pragma unroll
        for (int ks = 0; ks < 2; ks++) {
            int kb = ks * 8;
            uint32_t ahi[4][4], bhi[4][2];
            uint32_t alo[4][4], blo[4][2];
            #pragma unroll
            for (int mt = 0; mt < 4; mt++) {
                int m = wm + mt * 16;
                float f0 = As[buf][m + r][kb + cq];
                float f1 = As[buf][m + r + 8][kb + cq];
                float f2 = As[buf][m + r][kb + cq + 4];
                float f3 = As[buf][m + r + 8][kb + cq + 4];
                if (PRECISE) {
                    split_tf32(f0, ahi[mt][0], alo[mt][0]);
                    split_tf32(f1, ahi[mt][1], alo[mt][1]);
                    split_tf32(f2, ahi[mt][2], alo[mt][2]);
                    split_tf32(f3, ahi[mt][3], alo[mt][3]);
                } else {
                    ahi[mt][0] = f2tf32(f0); ahi[mt][1] = f2tf32(f1);
                    ahi[mt][2] = f2tf32(f2); ahi[mt][3] = f2tf32(f3);
                }
            }
            #pragma unroll
            for (int nt = 0; nt < 4; nt++) {
                int n = wn + nt * 8;
                float f0 = Bs[buf][n + r][kb + cq];
                float f1 = Bs[buf][n + r][kb + cq + 4];
                if (PRECISE) {
                    split_tf32(f0, bhi[nt][0], blo[nt][0]);
                    split_tf32(f1, bhi[nt][1], blo[nt][1]);
                } else {
                    bhi[nt][0] = f2tf32(f0); bhi[nt][1] = f2tf32(f1);
                }
            }
            #pragma unroll
            for (int mt = 0; mt < 4; mt++)
                #pragma unroll
                for (int nt = 0; nt < 4; nt++) {
                    mma8(acc[mt][nt], ahi[mt], bhi[nt]);
                    if (PRECISE) {
                        mma8(acc[mt][nt], ahi[mt], blo[nt]);
                        mma8(acc[mt][nt], alo[mt], bhi[nt]);
                    }
                }
        }
        __syncthreads();
        buf ^= 1;
    }

    // epilogue
    #pragma unroll
    for (int mt = 0; mt < 4; mt++) {
        int row0 = bm * 128 + wm + mt * 16 + r;
        #pragma unroll
        for (int nt = 0; nt < 4; nt++) {
            int col = bn * 128 + wn + nt * 8 + 2 * cq;
            float2 v0 = make_float2(acc[mt][nt][0], acc[mt][nt][1]);
            float2 v1 = make_float2(acc[mt][nt][2], acc[mt][nt][3]);
            if (HAS_BIAS) {
                float2 bb = *(const float2*)(bias + col);
                v0.x += bb.x; v0.y += bb.y; v1.x += bb.x; v1.y += bb.y;
            }
            size_t i0 = (size_t)row0 * N + col;
            size_t i1 = i0 + (size_t)8 * N;
            if (HAS_RES) {
                float2 r0 = *(const float2*)(res + i0);
                float2 r1 = *(const float2*)(res + i1);
                v0.x += r0.x; v0.y += r0.y; v1.x += r1.x; v1.y += r1.y;
            }
            *(float2*)(C + i0) = v0;
            *(float2*)(C + i1) = v1;
        }
    }
}

// ---------------- sliding-window attention -------------------------------
#define QS_STRIDE 65
#define SC_STRIDE 321
#define SC_OFF    (2 * 64 * QS_STRIDE)

__global__ void __launch_bounds__(256)
attn_kernel(const float* __restrict__ q, const float* __restrict__ k,
            const float* __restrict__ v, float* __restrict__ ao,
            float* __restrict__ attn_out) {
    extern __shared__ float sm[];
    float* Qs  = sm;                       // [d][qq] stride 65
    float* KVs = sm + 64 * QS_STRIDE;      // phase A: [d][kk]; phase D: [kk][d]
    float* sc  = sm + SC_OFF;              // [qq][slot] stride 321, 320 slots

    int q0 = blockIdx.x * 64;
    int bh = blockIdx.y;
    int b  = bh >> 4, h = bh & 15;
    int tid = threadIdx.x;
    int tx = tid & 15, ty = tid >> 4;
    const float scale = 0.125f;   // 1/sqrt(64)

    for (int t = tid; t < 64 * 64; t += 256) {
        int qq = t >> 6, d = t & 63;
        Qs[d * QS_STRIDE + qq] = q[((size_t)(b * SS + q0 + qq)) * DD + h * HDIM + d];
    }

    for (int c = 0; c < 5; c++) {
        int jb = q0 - 256 + c * 64;
        for (int t = tid; t < 64 * 64; t += 256) {
            int kk = t >> 6, d = t & 63;
            int j = jb + kk;
            KVs[d * QS_STRIDE + kk] =
                (j >= 0) ? k[((size_t)(b * SS + j)) * DD + h * HDIM + d] : 0.f;
        }
        __syncthreads();
        float acc[4][4];
        #pragma unroll
        for (int i = 0; i < 4; i++)
            #pragma unroll
            for (int j = 0; j < 4; j++) acc[i][j] = 0.f;
        #pragma unroll 8
        for (int d = 0; d < 64; d++) {
            float a[4], bb[4];
            #pragma unroll
            for (int i = 0; i < 4; i++) a[i]  = Qs [d * QS_STRIDE + ty * 4 + i];
            #pragma unroll
            for (int j = 0; j < 4; j++) bb[j] = KVs[d * QS_STRIDE + tx * 4 + j];
            #pragma unroll
            for (int i = 0; i < 4; i++)
                #pragma unroll
                for (int j = 0; j < 4; j++) acc[i][j] += a[i] * bb[j];
        }
        #pragma unroll
        for (int i = 0; i < 4; i++) {
            int qi = q0 + ty * 4 + i;
            #pragma unroll
            for (int j = 0; j < 4; j++) {
                int jj = jb + tx * 4 + j;
                bool valid = (jj >= 0) && (jj <= qi) && (qi - jj < WIN);
                sc[(ty * 4 + i) * SC_STRIDE + c * 64 + tx * 4 + j] =
                    valid ? acc[i][j] * scale : -1e30f;
            }
        }
        __syncthreads();
    }

    {
        int qq = tid >> 2, g = tid & 3;
        float* row = sc + qq * SC_STRIDE;
        float mx = -1e30f;
        for (int s = g; s < 320; s += 4) mx = fmaxf(mx, row[s]);
        mx = fmaxf(mx, __shfl_xor_sync(0xffffffffu, mx, 1));
        mx = fmaxf(mx, __shfl_xor_sync(0xffffffffu, mx, 2));
        float sum = 0.f;
        for (int s = g; s < 320; s += 4) {
            float e = expf(row[s] - mx);
            row[s] = e;
            sum += e;
        }
        sum += __shfl_xor_sync(0xffffffffu, sum, 1);
        sum += __shfl_xor_sync(0xffffffffu, sum, 2);
        float inv = 1.f / sum;
        for (int s = g; s < 320; s += 4) row[s] *= inv;
    }
    __syncthreads();

    for (int qq = 0; qq < 64; qq++) {
        int qi = q0 + qq;
        float* dst = attn_out + ((size_t)bh * SS + qi) * SS;
        const float* src = sc + qq * SC_STRIDE;
        float rr[4];
        #pragma unroll
        for (int u = 0; u < 4; u++) {
            int j = tid * 4 + u;
            bool in = (j <= qi) && (qi - j < WIN);
            rr[u] = in ? src[j - q0 + 256] : 0.f;
        }
        ((float4*)dst)[tid] = make_float4(rr[0], rr[1], rr[2], rr[3]);
    }

    float oacc[4][4];
    #pragma unroll
    for (int i = 0; i < 4; i++)
        #pragma unroll
        for (int j = 0; j < 4; j++) oacc[i][j] = 0.f;

    for (int c = 0; c < 5; c++) {
        int jb = q0 - 256 + c * 64;
        __syncthreads();
        for (int t = tid; t < 64 * 64; t += 256) {
            int kk = t >> 6, d = t & 63;
            int j = jb + kk;
            KVs[kk * QS_STRIDE + d] =
                (j >= 0) ? v[((size_t)(b * SS + j)) * DD + h * HDIM + d] : 0.f;
        }
        __syncthreads();
        #pragma unroll 8
        for (int kk = 0; kk < 64; kk++) {
            float p[4], bv[4];
            #pragma unroll
            for (int i = 0; i < 4; i++)
                p[i] = sc[(ty * 4 + i) * SC_STRIDE + c * 64 + kk];
            #pragma unroll
            for (int j = 0; j < 4; j++)
                bv[j] = KVs[kk * QS_STRIDE + tx * 4 + j];
            #pragma unroll
            for (int i = 0; i < 4; i++)
                #pragma unroll
                for (int j = 0; j < 4; j++) oacc[i][j] += p[i] * bv[j];
        }
    }

    #pragma unroll
    for (int i = 0; i < 4; i++) {
        size_t base = ((size_t)(b * SS + q0 + ty * 4 + i)) * DD + h * HDIM + tx * 4;
        *(float4*)(ao + base) = make_float4(oacc[i][0], oacc[i][1], oacc[i][2], oacc[i][3]);
    }
}

// ---------------- launcher -------------------------------------------------
extern "C" void kernel_launch(void* const* d_in, const int* in_sizes, int n_in,
                              void* d_out, int out_size) {
    const float* x   = (const float*)d_in[0];
    const float* wq  = (const float*)d_in[1];
    const float* bq  = (const float*)d_in[2];
    const float* wk  = (const float*)d_in[3];
    const float* bk  = (const float*)d_in[4];
    const float* wv  = (const float*)d_in[5];
    const float* bv  = (const float*)d_in[6];
    const float* wo  = (const float*)d_in[7];
    const float* bo  = (const float*)d_in[8];
    const float* anw = (const float*)d_in[9];
    const float* fnw = (const float*)d_in[10];
    const float* gw  = (const float*)d_in[11];
    const float* uw  = (const float*)d_in[12];
    const float* dw  = (const float*)d_in[13];

    float* outx = (float*)d_out;                       // [B,S,D]
    float* outa = outx + (size_t)MR * DD;              // [B,H,S,S]

    float *p_h, *p_q, *p_k, *p_v, *p_ao, *p_x1, *p_h2, *p_gate, *p_up;
    cudaGetSymbolAddress((void**)&p_h,    g_h);
    cudaGetSymbolAddress((void**)&p_q,    g_q);
    cudaGetSymbolAddress((void**)&p_k,    g_k);
    cudaGetSymbolAddress((void**)&p_v,    g_v);
    cudaGetSymbolAddress((void**)&p_ao,   g_ao);
    cudaGetSymbolAddress((void**)&p_x1,   g_x1);
    cudaGetSymbolAddress((void**)&p_h2,   g_h2);
    cudaGetSymbolAddress((void**)&p_gate, g_gate);
    cudaGetSymbolAddress((void**)&p_up,   g_up);

    const int attn_smem = (2 * 64 * QS_STRIDE + 64 * SC_STRIDE) * sizeof(float);
    cudaFuncSetAttribute(attn_kernel,
                         cudaFuncAttributeMaxDynamicSharedMemorySize, attn_smem);

    // 1) attn rmsnorm
    rmsnorm_kernel<<<MR, 256>>>(x, anw, p_h);

    // 2) QKV — one z=3 launch, PRECISE 3xTF32 for accurate probs downstream
    {
        GemmArgs a;
        a.w[0] = wq; a.w[1] = wk; a.w[2] = wv;
        a.b[0] = bq; a.b[1] = bk; a.b[2] = bv;
        a.c[0] = p_q; a.c[1] = p_k; a.c[2] = p_v;
        gemm_tf32<true, false, true><<<dim3(DD/128, MR/128, 3), 256>>>(
            p_h, a, nullptr, MR, DD, DD);
    }
    // 3) RoPE
    rope_kernel<<<(2 * MR * 512) / 256, 256>>>(p_q, p_k);
    // 4) attention (probs -> outa, context -> g_ao)
    attn_kernel<<<dim3(SS / 64, BB * HH), 256, attn_smem>>>(p_q, p_k, p_v, p_ao, outa);
    // 5) O proj + bias + residual
    {
        GemmArgs a;
        a.w[0] = wo; a.b[0] = bo; a.c[0] = p_x1;
        a.w[1] = a.w[2] = nullptr; a.b[1] = a.b[2] = nullptr; a.c[1] = a.c[2] = nullptr;
        gemm_tf32<true, true, false><<<dim3(DD/128, MR/128, 1), 256>>>(
            p_ao, a, x, MR, DD, DD);
    }
    // 6) ffn rmsnorm
    rmsnorm_kernel<<<MR, 256>>>(p_x1, fnw, p_h2);
    // 7) gate + up in one z=2 launch
    {
        GemmArgs a;
        a.w[0] = gw; a.w[1] = uw; a.w[2] = nullptr;
        a.b[0] = a.b[1] = a.b[2] = nullptr;
        a.c[0] = p_gate; a.c[1] = p_up; a.c[2] = nullptr;
        gemm_tf32<false, false, false><<<dim3(FF/128, MR/128, 2), 256>>>(
            p_h2, a, nullptr, MR, FF, DD);
    }
    // 8) act = silu(gate) * up  (in place into up)
    silu_mul_kernel<<<(MR * FF / 4) / 256, 256>>>(p_gate, p_up);
    // 9) down + residual -> final x
    {
        GemmArgs a;
        a.w[0] = dw; a.b[0] = nullptr; a.c[0] = outx;
        a.w[1] = a.w[2] = nullptr; a.b[1] = a.b[2] = nullptr; a.c[1] = a.c[2] = nullptr;
        gemm_tf32<false, true, false><<<dim3(DD/128, MR/128, 1), 256>>>(
            p_up, a, p_x1, MR, DD, FF);
    }
}

// round 3
// speedup vs baseline: 2.8925x; 1.1600x over previous
#include <cuda_runtime.h>
#include <cstdint>

// Problem constants
#define BB   2
#define SS   1024
#define DD   1024
#define HH   16
#define HDIM 64
#define WIN  256
#define FF   4096
#define MR   (BB*SS)   // 2048 rows

// ---------------- scratch (device globals; no allocation allowed) ----------
__device__ float g_h  [MR*DD];
__device__ float g_q  [MR*DD];
__device__ float g_k  [MR*DD];
__device__ float g_v  [MR*DD];
__device__ float g_ao [MR*DD];
__device__ float g_x1 [MR*DD];
__device__ float g_h2 [MR*DD];
__device__ float g_gate[MR*FF];
__device__ float g_up  [MR*FF];

// ---------------- common PTX helpers ---------------------------------------
__device__ __forceinline__ void cp16(void* smem_dst, const void* gsrc) {
    uint32_t s = (uint32_t)__cvta_generic_to_shared(smem_dst);
    asm volatile("cp.async.cg.shared.global [%0], [%1], 16;\n" :: "r"(s), "l"(gsrc));
}
__device__ __forceinline__ uint32_t f2tf32(float x) {
    uint32_t u;
    asm("cvt.rna.tf32.f32 %0, %1;" : "=r"(u) : "f"(x));
    return u;
}
__device__ __forceinline__ void split_tf32(float x, uint32_t& hi, uint32_t& lo) {
    hi = f2tf32(x);
    float rem = x - __uint_as_float(hi);
    lo = f2tf32(rem);
}
__device__ __forceinline__ void mma8(float* d, const uint32_t* a, const uint32_t* b) {
    asm volatile(
        "mma.sync.aligned.m16n8k8.row.col.f32.tf32.tf32.f32 "
        "{%0,%1,%2,%3}, {%4,%5,%6,%7}, {%8,%9}, {%0,%1,%2,%3};\n"
        : "+f"(d[0]), "+f"(d[1]), "+f"(d[2]), "+f"(d[3])
        : "r"(a[0]), "r"(a[1]), "r"(a[2]), "r"(a[3]), "r"(b[0]), "r"(b[1]));
}

// ---------------- RMSNorm: one block per row, 256 threads, D=1024 ----------
__global__ void rmsnorm_kernel(const float* __restrict__ x,
                               const float* __restrict__ w,
                               float* __restrict__ out) {
    int row = blockIdx.x;
    int tid = threadIdx.x;
    const float4 xv = ((const float4*)(x + (size_t)row * DD))[tid];
    float ss = xv.x*xv.x + xv.y*xv.y + xv.z*xv.z + xv.w*xv.w;
    #pragma unroll
    for (int o = 16; o; o >>= 1) ss += __shfl_xor_sync(0xffffffffu, ss, o);
    __shared__ float red[8];
    if ((tid & 31) == 0) red[tid >> 5] = ss;
    __syncthreads();
    if (tid < 32) {
        float v = (tid < 8) ? red[tid] : 0.f;
        #pragma unroll
        for (int o = 4; o; o >>= 1) v += __shfl_xor_sync(0xffffffffu, v, o);
        if (tid == 0) red[0] = v;
    }
    __syncthreads();
    float inv = rsqrtf(red[0] * (1.0f / DD) + 1e-6f);
    float4 wv = ((const float4*)w)[tid];
    float4 o4;
    o4.x = xv.x * inv * wv.x; o4.y = xv.y * inv * wv.y;
    o4.z = xv.z * inv * wv.z; o4.w = xv.w * inv * wv.w;
    ((float4*)(out + (size_t)row * DD))[tid] = o4;
}

// ---------------- RoPE in-place on q and k (pair per thread) ---------------
__global__ void rope_kernel(float* __restrict__ q, float* __restrict__ k) {
    int t = blockIdx.x * blockDim.x + threadIdx.x;
    int total = MR * 512;
    float* p = (t < total) ? q : k;
    int u = (t < total) ? t : (t - total);
    int m  = u >> 9;
    int pr = u & 511;
    int hh = pr >> 5;
    int i  = pr & 31;
    int s  = m & (SS - 1);
    float inv = expf(-(float)i * 0.28782313662425576f);   // ln(10000)/32
    float ang = (float)s * inv;
    float c = cosf(ang), sn = sinf(ang);
    size_t base = (size_t)m * DD + hh * HDIM + i;
    float x1 = p[base];
    float x2 = p[base + 32];
    p[base]      = x1 * c - x2 * sn;
    p[base + 32] = x2 * c + x1 * sn;
}

// ---------------- silu(gate) * up, in place into up ------------------------
__global__ void silu_mul_kernel(const float* __restrict__ g, float* __restrict__ u) {
    int i = blockIdx.x * blockDim.x + threadIdx.x;
    float4 gv = ((const float4*)g)[i];
    float4 uv = ((float4*)u)[i];
    uv.x *= gv.x / (1.f + expf(-gv.x));
    uv.y *= gv.y / (1.f + expf(-gv.y));
    uv.z *= gv.z / (1.f + expf(-gv.z));
    uv.w *= gv.w / (1.f + expf(-gv.w));
    ((float4*)u)[i] = uv;
}

// ---------------- tf32 tensor-core GEMM, 3-stage cp.async pipeline ---------
// C[M,N] = A[M,K] @ W[N,K]^T (+bias, +res). 128x128x16 tile, 256 threads,
// 8 warps (2x4), warp tile 64x32, mma.m16n8k8.tf32 with rna rounding.

struct GemmArgs {
    const float* w[3];
    const float* b[3];
    float* c[3];
};

#define GS_TILE (128 * 20)              // floats per stage per matrix
#define GEMM_SMEM (6 * GS_TILE * 4)     // 3 stages x (A+B)

template<bool HAS_BIAS, bool HAS_RES>
__global__ void __launch_bounds__(256)
gemm_tf32(const float* __restrict__ A, GemmArgs args,
          const float* __restrict__ res, int M, int N, int K) {
    const float* __restrict__ W = args.w[blockIdx.z];
    const float* __restrict__ bias = args.b[blockIdx.z];
    float* __restrict__ C = args.c[blockIdx.z];

    extern __shared__ float smg[];
    float* Asb = smg;                   // 3 stages of [128][20]
    float* Bsb = smg + 3 * GS_TILE;

    int bm = blockIdx.y, bn = blockIdx.x;
    int tid = threadIdx.x;
    int lane = tid & 31, warp = tid >> 5;
    int wm = (warp >> 2) * 64;
    int wn = (warp & 3) * 32;
    int r = lane >> 2, cq = lane & 3;

    float acc[4][4][4];
    #pragma unroll
    for (int i = 0; i < 4; i++)
        #pragma unroll
        for (int j = 0; j < 4; j++)
            #pragma unroll
            for (int t = 0; t < 4; t++) acc[i][j][t] = 0.f;

    const float* Abase = A + (size_t)(bm * 128) * K;
    const float* Wbase = W + (size_t)(bn * 128) * K;
    int tr  = tid >> 2;
    int tkc = (tid & 3) << 2;

    auto load_tile = [&](int st, int k0) {
        float* As = Asb + st * GS_TILE;
        float* Bs = Bsb + st * GS_TILE;
        cp16(&As[tr * 20 + tkc],        Abase + (size_t)tr * K + k0 + tkc);
        cp16(&As[(tr + 64) * 20 + tkc], Abase + (size_t)(tr + 64) * K + k0 + tkc);
        cp16(&Bs[tr * 20 + tkc],        Wbase + (size_t)tr * K + k0 + tkc);
        cp16(&Bs[(tr + 64) * 20 + tkc], Wbase + (size_t)(tr + 64) * K + k0 + tkc);
    };

    int nk = K >> 4;
    load_tile(0, 0);
    asm volatile("cp.async.commit_group;\n" ::);
    load_tile(1, 16);
    asm volatile("cp.async.commit_group;\n" ::);

    int s = 0;
    for (int kt = 0; kt < nk; kt++) {
        if (kt + 1 < nk) {
            asm volatile("cp.async.wait_group 1;\n" ::);
        } else {
            asm volatile("cp.async.wait_group 0;\n" ::);
        }
        __syncthreads();
        if (kt + 2 < nk) {
            int s2 = s + 2; if (s2 >= 3) s2 -= 3;
            load_tile(s2, (kt + 2) * 16);
            asm volatile("cp.async.commit_group;\n" ::);
        }

        const float* As = Asb + s * GS_TILE;
        const float* Bs = Bsb + s * GS_TILE;
        #pragma unroll
        for (int ks = 0; ks < 2; ks++) {
            int kb = ks * 8;
            uint32_t ah[4][4], bh[4][2];
            #pragma unroll
            for (int mt = 0; mt < 4; mt++) {
                int m = wm + mt * 16;
                ah[mt][0] = f2tf32(As[(m + r)     * 20 + kb + cq]);
                ah[mt][1] = f2tf32(As[(m + r + 8) * 20 + kb + cq]);
                ah[mt][2] = f2tf32(As[(m + r)     * 20 + kb + cq + 4]);
                ah[mt][3] = f2tf32(As[(m + r + 8) * 20 + kb + cq + 4]);
            }
            #pragma unroll
            for (int nt = 0; nt < 4; nt++) {
                int n = wn + nt * 8;
                bh[nt][0] = f2tf32(Bs[(n + r) * 20 + kb + cq]);
                bh[nt][1] = f2tf32(Bs[(n + r) * 20 + kb + cq + 4]);
            }
            #pragma unroll
            for (int mt = 0; mt < 4; mt++)
                #pragma unroll
                for (int nt = 0; nt < 4; nt++)
                    mma8(acc[mt][nt], ah[mt], bh[nt]);
        }
        s = s + 1; if (s >= 3) s -= 3;
    }

    // epilogue
    #pragma unroll
    for (int mt = 0; mt < 4; mt++) {
        int row0 = bm * 128 + wm + mt * 16 + r;
        #pragma unroll
        for (int nt = 0; nt < 4; nt++) {
            int col = bn * 128 + wn + nt * 8 + 2 * cq;
            float2 v0 = make_float2(acc[mt][nt][0], acc[mt][nt][1]);
            float2 v1 = make_float2(acc[mt][nt][2], acc[mt][nt][3]);
            if (HAS_BIAS) {
                float2 bb = *(const float2*)(bias + col);
                v0.x += bb.x; v0.y += bb.y; v1.x += bb.x; v1.y += bb.y;
            }
            size_t i0 = (size_t)row0 * N + col;
            size_t i1 = i0 + (size_t)8 * N;
            if (HAS_RES) {
                float2 r0 = *(const float2*)(res + i0);
                float2 r1 = *(const float2*)(res + i1);
                v0.x += r0.x; v0.y += r0.y; v1.x += r1.x; v1.y += r1.y;
            }
            *(float2*)(C + i0) = v0;
            *(float2*)(C + i1) = v1;
        }
    }
}

// ---------------- sliding-window attention (tensor-core) -------------------
// Block: 64 queries of one (b,h). smem: Qs[64][68] + KVs[64][68] + sc[64][321]
#define AQ_STR 68
#define ASC_STR 321
#define ATTN_SMEM ((2 * 64 * AQ_STR + 64 * ASC_STR) * 4)

__global__ void __launch_bounds__(256)
attn_kernel(const float* __restrict__ q, const float* __restrict__ k,
            const float* __restrict__ v, float* __restrict__ ao,
            float* __restrict__ attn_out) {
    extern __shared__ float sm[];
    float* Qs  = sm;                       // [qq][d] stride 68
    float* KVs = sm + 64 * AQ_STR;         // A: [kk][d]; D: [d][kk], stride 68
    float* sc  = sm + 2 * 64 * AQ_STR;     // [qq][slot] stride 321

    int q0 = blockIdx.x * 64;
    int bh = blockIdx.y;
    int b  = bh >> 4, h = bh & 15;
    int tid = threadIdx.x;
    int lane = tid & 31, warp = tid >> 5;
    int wm = (warp & 3) * 16;              // query tile offset
    int wn = (warp >> 2) * 32;             // key/dim tile offset
    int r = lane >> 2, cq = lane & 3;
    const float scale = 0.125f;            // 1/sqrt(64)

    // load Q tile [qq][d] (coalesced: consecutive tid -> consecutive d)
    for (int t = tid; t < 64 * 64; t += 256) {
        int qq = t >> 6, d = t & 63;
        Qs[qq * AQ_STR + d] = q[((size_t)(b * SS + q0 + qq)) * DD + h * HDIM + d];
    }

    // -------- Phase A: scores via mma (precise 3xTF32) --------------------
    for (int c = 0; c < 5; c++) {
        int jb = q0 - 256 + c * 64;
        __syncthreads();   // prior chunk's mma reads of KVs done
        for (int t = tid; t < 64 * 64; t += 256) {
            int kk = t >> 6, d = t & 63;
            int j = jb + kk;
            KVs[kk * AQ_STR + d] =
                (j >= 0) ? k[((size_t)(b * SS + j)) * DD + h * HDIM + d] : 0.f;
        }
        __syncthreads();

        float acc[4][4];
        #pragma unroll
        for (int i = 0; i < 4; i++)
            #pragma unroll
            for (int j = 0; j < 4; j++) acc[i][j] = 0.f;

        #pragma unroll
        for (int kb = 0; kb < 64; kb += 8) {
            uint32_t ah[4], al[4];
            split_tf32(Qs[(wm + r)     * AQ_STR + kb + cq],     ah[0], al[0]);
            split_tf32(Qs[(wm + r + 8) * AQ_STR + kb + cq],     ah[1], al[1]);
            split_tf32(Qs[(wm + r)     * AQ_STR + kb + cq + 4], ah[2], al[2]);
            split_tf32(Qs[(wm + r + 8) * AQ_STR + kb + cq + 4], ah[3], al[3]);
            #pragma unroll
            for (int nt = 0; nt < 4; nt++) {
                uint32_t bh2[2], bl2[2];
                split_tf32(KVs[(wn + nt * 8 + r) * AQ_STR + kb + cq],     bh2[0], bl2[0]);
                split_tf32(KVs[(wn + nt * 8 + r) * AQ_STR + kb + cq + 4], bh2[1], bl2[1]);
                mma8(acc[nt], ah, bh2);
                mma8(acc[nt], ah, bl2);
                mma8(acc[nt], al, bh2);
            }
        }

        // masked score write
        #pragma unroll
        for (int nt = 0; nt < 4; nt++) {
            int jl = wn + nt * 8 + 2 * cq;
            #pragma unroll
            for (int u = 0; u < 2; u++) {          // rows r, r+8
                int qq = wm + r + u * 8;
                int qi = q0 + qq;
                #pragma unroll
                for (int w2 = 0; w2 < 2; w2++) {
                    int jj = jb + jl + w2;
                    bool valid = (jj >= 0) && (jj <= qi) && (qi - jj < WIN);
                    sc[qq * ASC_STR + c * 64 + jl + w2] =
                        valid ? acc[nt][u * 2 + w2] * scale : -1e30f;
                }
            }
        }
    }
    __syncthreads();

    // -------- Phase B: softmax per query row (4 threads / row) ------------
    {
        int qq = tid >> 2, g = tid & 3;
        float* row = sc + qq * ASC_STR;
        float mx = -1e30f;
        for (int s = g; s < 320; s += 4) mx = fmaxf(mx, row[s]);
        mx = fmaxf(mx, __shfl_xor_sync(0xffffffffu, mx, 1));
        mx = fmaxf(mx, __shfl_xor_sync(0xffffffffu, mx, 2));
        float sum = 0.f;
        for (int s = g; s < 320; s += 4) {
            float e = expf(row[s] - mx);
            row[s] = e;
            sum += e;
        }
        sum += __shfl_xor_sync(0xffffffffu, sum, 1);
        sum += __shfl_xor_sync(0xffffffffu, sum, 2);
        float inv = 1.f / sum;
        for (int s = g; s < 320; s += 4) row[s] *= inv;
    }
    __syncthreads();

    // -------- Phase C: write full attn rows (zeros + probs) ---------------
    for (int qq = 0; qq < 64; qq++) {
        int qi = q0 + qq;
        float* dst = attn_out + ((size_t)bh * SS + qi) * SS;
        const float* src = sc + qq * ASC_STR;
        float rr[4];
        #pragma unroll
        for (int u = 0; u < 4; u++) {
            int j = tid * 4 + u;
            bool in = (j <= qi) && (qi - j < WIN);
            rr[u] = in ? src[j - q0 + 256] : 0.f;
        }
        ((float4*)dst)[tid] = make_float4(rr[0], rr[1], rr[2], rr[3]);
    }

    // -------- Phase D: out = P @ V via mma --------------------------------
    float oacc[4][4];
    #pragma unroll
    for (int i = 0; i < 4; i++)
        #pragma unroll
        for (int j = 0; j < 4; j++) oacc[i][j] = 0.f;

    for (int c = 0; c < 5; c++) {
        int jb = q0 - 256 + c * 64;
        __syncthreads();
        // V^T tile: Vs[d][kk] (coalesced global reads; minor smem write conflicts)
        for (int t = tid; t < 64 * 64; t += 256) {
            int kk = t >> 6, d = t & 63;
            int j = jb + kk;
            KVs[d * AQ_STR + kk] =
                (j >= 0) ? v[((size_t)(b * SS + j)) * DD + h * HDIM + d] : 0.f;
        }
        __syncthreads();
        #pragma unroll
        for (int kb = 0; kb < 64; kb += 8) {
            uint32_t ah[4];
            ah[0] = f2tf32(sc[(wm + r)     * ASC_STR + c * 64 + kb + cq]);
            ah[1] = f2tf32(sc[(wm + r + 8) * ASC_STR + c * 64 + kb + cq]);
            ah[2] = f2tf32(sc[(wm + r)     * ASC_STR + c * 64 + kb + cq + 4]);
            ah[3] = f2tf32(sc[(wm + r + 8) * ASC_STR + c * 64 + kb + cq + 4]);
            #pragma unroll
            for (int nt = 0; nt < 4; nt++) {
                uint32_t bb[2];
                bb[0] = f2tf32(KVs[(wn + nt * 8 + r) * AQ_STR + kb + cq]);
                bb[1] = f2tf32(KVs[(wn + nt * 8 + r) * AQ_STR + kb + cq + 4]);
                mma8(oacc[nt], ah, bb);
            }
        }
    }

    #pragma unroll
    for (int nt = 0; nt < 4; nt++) {
        int d0 = wn + nt * 8 + 2 * cq;
        size_t b0 = ((size_t)(b * SS + q0 + wm + r))     * DD + h * HDIM + d0;
        size_t b1 = ((size_t)(b * SS + q0 + wm + r + 8)) * DD + h * HDIM + d0;
        *(float2*)(ao + b0) = make_float2(oacc[nt][0], oacc[nt][1]);
        *(float2*)(ao + b1) = make_float2(oacc[nt][2], oacc[nt][3]);
    }
}

// ---------------- launcher -------------------------------------------------
extern "C" void kernel_launch(void* const* d_in, const int* in_sizes, int n_in,
                              void* d_out, int out_size) {
    const float* x   = (const float*)d_in[0];
    const float* wq  = (const float*)d_in[1];
    const float* bq  = (const float*)d_in[2];
    const float* wk  = (const float*)d_in[3];
    const float* bk  = (const float*)d_in[4];
    const float* wv  = (const float*)d_in[5];
    const float* bv  = (const float*)d_in[6];
    const float* wo  = (const float*)d_in[7];
    const float* bo  = (const float*)d_in[8];
    const float* anw = (const float*)d_in[9];
    const float* fnw = (const float*)d_in[10];
    const float* gw  = (const float*)d_in[11];
    const float* uw  = (const float*)d_in[12];
    const float* dw  = (const float*)d_in[13];

    float* outx = (float*)d_out;                       // [B,S,D]
    float* outa = outx + (size_t)MR * DD;              // [B,H,S,S]

    float *p_h, *p_q, *p_k, *p_v, *p_ao, *p_x1, *p_h2, *p_gate, *p_up;
    cudaGetSymbolAddress((void**)&p_h,    g_h);
    cudaGetSymbolAddress((void**)&p_q,    g_q);
    cudaGetSymbolAddress((void**)&p_k,    g_k);
    cudaGetSymbolAddress((void**)&p_v,    g_v);
    cudaGetSymbolAddress((void**)&p_ao,   g_ao);
    cudaGetSymbolAddress((void**)&p_x1,   g_x1);
    cudaGetSymbolAddress((void**)&p_h2,   g_h2);
    cudaGetSymbolAddress((void**)&p_gate, g_gate);
    cudaGetSymbolAddress((void**)&p_up,   g_up);

    cudaFuncSetAttribute(attn_kernel,
                         cudaFuncAttributeMaxDynamicSharedMemorySize, ATTN_SMEM);
    cudaFuncSetAttribute(gemm_tf32<true, false>,
                         cudaFuncAttributeMaxDynamicSharedMemorySize, GEMM_SMEM);
    cudaFuncSetAttribute(gemm_tf32<true, true>,
                         cudaFuncAttributeMaxDynamicSharedMemorySize, GEMM_SMEM);
    cudaFuncSetAttribute(gemm_tf32<false, false>,
                         cudaFuncAttributeMaxDynamicSharedMemorySize, GEMM_SMEM);
    cudaFuncSetAttribute(gemm_tf32<false, true>,
                         cudaFuncAttributeMaxDynamicSharedMemorySize, GEMM_SMEM);

    // 1) attn rmsnorm
    rmsnorm_kernel<<<MR, 256>>>(x, anw, p_h);

    // 2) QKV — one z=3 launch (single-pass tf32, rna)
    {
        GemmArgs a;
        a.w[0] = wq; a.w[1] = wk; a.w[2] = wv;
        a.b[0] = bq; a.b[1] = bk; a.b[2] = bv;
        a.c[0] = p_q; a.c[1] = p_k; a.c[2] = p_v;
        gemm_tf32<true, false><<<dim3(DD/128, MR/128, 3), 256, GEMM_SMEM>>>(
            p_h, a, nullptr, MR, DD, DD);
    }
    // 3) RoPE
    rope_kernel<<<(2 * MR * 512) / 256, 256>>>(p_q, p_k);
    // 4) attention (probs -> outa, context -> g_ao)
    attn_kernel<<<dim3(SS / 64, BB * HH), 256, ATTN_SMEM>>>(p_q, p_k, p_v, p_ao, outa);
    // 5) O proj + bias + residual
    {
        GemmArgs a;
        a.w[0] = wo; a.b[0] = bo; a.c[0] = p_x1;
        a.w[1] = a.w[2] = nullptr; a.b[1] = a.b[2] = nullptr; a.c[1] = a.c[2] = nullptr;
        gemm_tf32<true, true><<<dim3(DD/128, MR/128, 1), 256, GEMM_SMEM>>>(
            p_ao, a, x, MR, DD, DD);
    }
    // 6) ffn rmsnorm
    rmsnorm_kernel<<<MR, 256>>>(p_x1, fnw, p_h2);
    // 7) gate + up in one z=2 launch
    {
        GemmArgs a;
        a.w[0] = gw; a.w[1] = uw; a.w[2] = nullptr;
        a.b[0] = a.b[1] = a.b[2] = nullptr;
        a.c[0] = p_gate; a.c[1] = p_up; a.c[2] = nullptr;
        gemm_tf32<false, false><<<dim3(FF/128, MR/128, 2), 256, GEMM_SMEM>>>(
            p_h2, a, nullptr, MR, FF, DD);
    }
    // 8) act = silu(gate) * up  (in place into up)
    silu_mul_kernel<<<(MR * FF / 4) / 256, 256>>>(p_gate, p_up);
    // 9) down + residual -> final x
    {
        GemmArgs a;
        a.w[0] = dw; a.b[0] = nullptr; a.c[0] = outx;
        a.w[1] = a.w[2] = nullptr; a.b[1] = a.b[2] = nullptr; a.c[1] = a.c[2] = nullptr;
        gemm_tf32<false, true><<<dim3(DD/128, MR/128, 1), 256, GEMM_SMEM>>>(
            p_up, a, p_x1, MR, DD, FF);
    }
}

// round 5
// speedup vs baseline: 3.1899x; 1.1028x over previous
#include <cuda_runtime.h>
#include <cstdint>

// Problem constants
#define BB   2
#define SS   1024
#define DD   1024
#define HH   16
#define HDIM 64
#define WIN  256
#define FF   4096
#define MR   (BB*SS)   // 2048 rows

// ---------------- scratch (device globals; no allocation allowed) ----------
__device__ float g_h  [MR*DD];
__device__ float g_q  [MR*DD];
__device__ float g_k  [MR*DD];
__device__ float g_v  [MR*DD];
__device__ float g_ao [MR*DD];
__device__ float g_x1 [MR*DD];
__device__ float g_h2 [MR*DD];
__device__ float g_gate[MR*FF];
__device__ float g_up  [MR*FF];
__device__ float g_wr [16*1024*1024];   // rounded weights: wq wk wv wo gw uw dw

// ---------------- common PTX helpers ---------------------------------------
__device__ __forceinline__ void cp16(void* smem_dst, const void* gsrc) {
    uint32_t s = (uint32_t)__cvta_generic_to_shared(smem_dst);
    asm volatile("cp.async.cg.shared.global [%0], [%1], 16;\n" :: "r"(s), "l"(gsrc));
}
__device__ __forceinline__ uint32_t f2tf32(float x) {
    uint32_t u;
    asm("cvt.rna.tf32.f32 %0, %1;" : "=r"(u) : "f"(x));
    return u;
}
__device__ __forceinline__ float rnd_tf32(float x) {
    return __uint_as_float(f2tf32(x));
}
__device__ __forceinline__ void split_tf32(float x, uint32_t& hi, uint32_t& lo) {
    hi = f2tf32(x);
    float rem = x - __uint_as_float(hi);
    lo = f2tf32(rem);
}
__device__ __forceinline__ void mma8(float* d, const uint32_t* a, const uint32_t* b) {
    asm volatile(
        "mma.sync.aligned.m16n8k8.row.col.f32.tf32.tf32.f32 "
        "{%0,%1,%2,%3}, {%4,%5,%6,%7}, {%8,%9}, {%0,%1,%2,%3};\n"
        : "+f"(d[0]), "+f"(d[1]), "+f"(d[2]), "+f"(d[3])
        : "r"(a[0]), "r"(a[1]), "r"(a[2]), "r"(a[3]), "r"(b[0]), "r"(b[1]));
}

// ---------------- elementwise kernels ---------------------------------------
__global__ void round_tf32_kernel(const float4* __restrict__ in,
                                  float4* __restrict__ out, int n4) {
    int i = blockIdx.x * 256 + threadIdx.x;
    if (i < n4) {
        float4 v = in[i];
        v.x = rnd_tf32(v.x); v.y = rnd_tf32(v.y);
        v.z = rnd_tf32(v.z); v.w = rnd_tf32(v.w);
        out[i] = v;
    }
}

__global__ void rmsnorm_kernel(const float* __restrict__ x,
                               const float* __restrict__ w,
                               float* __restrict__ out) {
    int row = blockIdx.x;
    int tid = threadIdx.x;
    const float4 xv = ((const float4*)(x + (size_t)row * DD))[tid];
    float ss = xv.x*xv.x + xv.y*xv.y + xv.z*xv.z + xv.w*xv.w;
    #pragma unroll
    for (int o = 16; o; o >>= 1) ss += __shfl_xor_sync(0xffffffffu, ss, o);
    __shared__ float red[8];
    if ((tid & 31) == 0) red[tid >> 5] = ss;
    __syncthreads();
    if (tid < 32) {
        float v = (tid < 8) ? red[tid] : 0.f;
        #pragma unroll
        for (int o = 4; o; o >>= 1) v += __shfl_xor_sync(0xffffffffu, v, o);
        if (tid == 0) red[0] = v;
    }
    __syncthreads();
    float inv = rsqrtf(red[0] * (1.0f / DD) + 1e-6f);
    float4 wv = ((const float4*)w)[tid];
    float4 o4;
    o4.x = rnd_tf32(xv.x * inv * wv.x); o4.y = rnd_tf32(xv.y * inv * wv.y);
    o4.z = rnd_tf32(xv.z * inv * wv.z); o4.w = rnd_tf32(xv.w * inv * wv.w);
    ((float4*)(out + (size_t)row * DD))[tid] = o4;
}

__global__ void rope_kernel(float* __restrict__ q, float* __restrict__ k) {
    int t = blockIdx.x * blockDim.x + threadIdx.x;
    int total = MR * 512;
    float* p = (t < total) ? q : k;
    int u = (t < total) ? t : (t - total);
    int m  = u >> 9;
    int pr = u & 511;
    int hh = pr >> 5;
    int i  = pr & 31;
    int s  = m & (SS - 1);
    float inv = expf(-(float)i * 0.28782313662425576f);   // ln(10000)/32
    float ang = (float)s * inv;
    float c = cosf(ang), sn = sinf(ang);
    size_t base = (size_t)m * DD + hh * HDIM + i;
    float x1 = p[base];
    float x2 = p[base + 32];
    p[base]      = x1 * c - x2 * sn;
    p[base + 32] = x2 * c + x1 * sn;
}

__global__ void silu_mul_kernel(const float* __restrict__ g, float* __restrict__ u) {
    int i = blockIdx.x * blockDim.x + threadIdx.x;
    float4 gv = ((const float4*)g)[i];
    float4 uv = ((float4*)u)[i];
    uv.x = rnd_tf32(uv.x * gv.x / (1.f + expf(-gv.x)));
    uv.y = rnd_tf32(uv.y * gv.y / (1.f + expf(-gv.y)));
    uv.z = rnd_tf32(uv.z * gv.z / (1.f + expf(-gv.z)));
    uv.w = rnd_tf32(uv.w * gv.w / (1.f + expf(-gv.w)));
    ((float4*)u)[i] = uv;
}

// ---------------- tf32 tensor-core GEMM, 3-stage cp.async pipeline ---------
// C[M,N] = A[M,K] @ W[N,K]^T (+bias, +res). 128x128x16 tile, 256 threads,
// 8 warps (2x4), warp tile 64x32, mma.m16n8k8.tf32.
// All A/W data pre-rounded to tf32 (rna) => raw bits fed to mma (no cvt).

struct GemmArgs {
    const float* w[3];
    const float* b[3];
    float* c[3];
};

#define GS_TILE (128 * 20)              // floats per stage per matrix
#define GEMM_SMEM (6 * GS_TILE * 4)     // 3 stages x (A+B)

template<bool HAS_BIAS, bool HAS_RES>
__global__ void __launch_bounds__(256)
gemm_tf32(const float* __restrict__ A, GemmArgs args,
          const float* __restrict__ res, int M, int N, int K) {
    const float* __restrict__ W = args.w[blockIdx.z];
    const float* __restrict__ bias = args.b[blockIdx.z];
    float* __restrict__ C = args.c[blockIdx.z];

    extern __shared__ float smg[];
    float* Asb = smg;                   // 3 stages of [128][20]
    float* Bsb = smg + 3 * GS_TILE;

    int bm = blockIdx.y, bn = blockIdx.x;
    int tid = threadIdx.x;
    int lane = tid & 31, warp = tid >> 5;
    int wm = (warp >> 2) * 64;
    int wn = (warp & 3) * 32;
    int r = lane >> 2, cq = lane & 3;

    float acc[4][4][4];
    #pragma unroll
    for (int i = 0; i < 4; i++)
        #pragma unroll
        for (int j = 0; j < 4; j++)
            #pragma unroll
            for (int t = 0; t < 4; t++) acc[i][j][t] = 0.f;

    const float* Abase = A + (size_t)(bm * 128) * K;
    const float* Wbase = W + (size_t)(bn * 128) * K;
    int tr  = tid >> 2;
    int tkc = (tid & 3) << 2;

    auto load_tile = [&](int st, int k0) {
        float* As = Asb + st * GS_TILE;
        float* Bs = Bsb + st * GS_TILE;
        cp16(&As[tr * 20 + tkc],        Abase + (size_t)tr * K + k0 + tkc);
        cp16(&As[(tr + 64) * 20 + tkc], Abase + (size_t)(tr + 64) * K + k0 + tkc);
        cp16(&Bs[tr * 20 + tkc],        Wbase + (size_t)tr * K + k0 + tkc);
        cp16(&Bs[(tr + 64) * 20 + tkc], Wbase + (size_t)(tr + 64) * K + k0 + tkc);
    };

    int nk = K >> 4;
    load_tile(0, 0);
    asm volatile("cp.async.commit_group;\n" ::);
    load_tile(1, 16);
    asm volatile("cp.async.commit_group;\n" ::);

    int s = 0;
    for (int kt = 0; kt < nk; kt++) {
        if (kt + 1 < nk) {
            asm volatile("cp.async.wait_group 1;\n" ::);
        } else {
            asm volatile("cp.async.wait_group 0;\n" ::);
        }
        __syncthreads();
        if (kt + 2 < nk) {
            int s2 = s + 2; if (s2 >= 3) s2 -= 3;
            load_tile(s2, (kt + 2) * 16);
            asm volatile("cp.async.commit_group;\n" ::);
        }

        const float* As = Asb + s * GS_TILE;
        const float* Bs = Bsb + s * GS_TILE;
        #pragma unroll
        for (int ks = 0; ks < 2; ks++) {
            int kb = ks * 8;
            uint32_t ah[4][4], bh[4][2];
            #pragma unroll
            for (int mt = 0; mt < 4; mt++) {
                int m = wm + mt * 16;
                ah[mt][0] = __float_as_uint(As[(m + r)     * 20 + kb + cq]);
                ah[mt][1] = __float_as_uint(As[(m + r + 8) * 20 + kb + cq]);
                ah[mt][2] = __float_as_uint(As[(m + r)     * 20 + kb + cq + 4]);
                ah[mt][3] = __float_as_uint(As[(m + r + 8) * 20 + kb + cq + 4]);
            }
            #pragma unroll
            for (int nt = 0; nt < 4; nt++) {
                int n = wn + nt * 8;
                bh[nt][0] = __float_as_uint(Bs[(n + r) * 20 + kb + cq]);
                bh[nt][1] = __float_as_uint(Bs[(n + r) * 20 + kb + cq + 4]);
            }
            #pragma unroll
            for (int mt = 0; mt < 4; mt++)
                #pragma unroll
                for (int nt = 0; nt < 4; nt++)
                    mma8(acc[mt][nt], ah[mt], bh[nt]);
        }
        s = s + 1; if (s >= 3) s -= 3;
    }

    // epilogue
    #pragma unroll
    for (int mt = 0; mt < 4; mt++) {
        int row0 = bm * 128 + wm + mt * 16 + r;
        #pragma unroll
        for (int nt = 0; nt < 4; nt++) {
            int col = bn * 128 + wn + nt * 8 + 2 * cq;
            float2 v0 = make_float2(acc[mt][nt][0], acc[mt][nt][1]);
            float2 v1 = make_float2(acc[mt][nt][2], acc[mt][nt][3]);
            if (HAS_BIAS) {
                float2 bb = *(const float2*)(bias + col);
                v0.x += bb.x; v0.y += bb.y; v1.x += bb.x; v1.y += bb.y;
            }
            size_t i0 = (size_t)row0 * N + col;
            size_t i1 = i0 + (size_t)8 * N;
            if (HAS_RES) {
                float2 r0 = *(const float2*)(res + i0);
                float2 r1 = *(const float2*)(res + i1);
                v0.x += r0.x; v0.y += r0.y; v1.x += r1.x; v1.y += r1.y;
            }
            *(float2*)(C + i0) = v0;
            *(float2*)(C + i1) = v1;
        }
    }
}

// ---------------- sliding-window attention (512 threads) -------------------
#define AQ_STR 68
#define ASC_STR 321
#define A_KV0 (64 * AQ_STR)
#define A_KV1 (2 * 64 * AQ_STR)
#define A_SC  (3 * 64 * AQ_STR)
#define ATTN_SMEM ((3 * 64 * AQ_STR + 64 * ASC_STR) * 4)

__global__ void __launch_bounds__(512)
attn_kernel(const float* __restrict__ q, const float* __restrict__ k,
            const float* __restrict__ v, float* __restrict__ ao,
            float* __restrict__ attn_out) {
    extern __shared__ float sm[];
    float* Qs = sm;
    float* KVb[2] = { sm + A_KV0, sm + A_KV1 };
    float* sc = sm + A_SC;

    int q0 = blockIdx.x * 64;
    int bh = blockIdx.y;
    int b  = bh >> 4, h = bh & 15;
    int tid = threadIdx.x;
    int lane = tid & 31, warp = tid >> 5;
    int wq = (warp & 3) * 16;            // query tile
    int wn = (warp >> 2) * 16;           // key/dim tile
    int r = lane >> 2, cq = lane & 3;
    const float scale = 0.125f;

    const float* kbase = k + (size_t)(b * SS) * DD + h * HDIM;
    const float* vbase = v + (size_t)(b * SS) * DD + h * HDIM;

    // load Q tile [qq][d]
    for (int t = tid; t < 64 * 64; t += 512) {
        int qq = t >> 6, d = t & 63;
        Qs[qq * AQ_STR + d] = q[((size_t)(b * SS + q0 + qq)) * DD + h * HDIM + d];
    }

    auto loadKV = [&](const float* base, float* dst, int jb) {
        #pragma unroll
        for (int i = 0; i < 2; i++) {
            int ch = tid + 512 * i;
            int kk = ch >> 4, dq = (ch & 15) * 4;
            int j = jb + kk;
            if (j >= 0) cp16(&dst[kk * AQ_STR + dq], base + (size_t)j * DD + dq);
            else *(float4*)&dst[kk * AQ_STR + dq] = make_float4(0.f, 0.f, 0.f, 0.f);
        }
    };

    // -------- Phase A: scores (precise 3xTF32), double-buffered K ---------
    loadKV(kbase, KVb[0], q0 - 256);
    asm volatile("cp.async.commit_group;\n" ::);
    for (int c = 0; c < 5; c++) {
        if (c < 4) {
            loadKV(kbase, KVb[(c + 1) & 1], q0 - 256 + (c + 1) * 64);
            asm volatile("cp.async.commit_group;\n" ::);
            asm volatile("cp.async.wait_group 1;\n" ::);
        } else {
            asm volatile("cp.async.wait_group 0;\n" ::);
        }
        __syncthreads();
        const float* Ks = KVb[c & 1];

        float acc[2][4];
        #pragma unroll
        for (int i = 0; i < 2; i++)
            #pragma unroll
            for (int j = 0; j < 4; j++) acc[i][j] = 0.f;

        #pragma unroll
        for (int kb = 0; kb < 64; kb += 8) {
            uint32_t ah[4], al[4];
            split_tf32(Qs[(wq + r)     * AQ_STR + kb + cq],     ah[0], al[0]);
            split_tf32(Qs[(wq + r + 8) * AQ_STR + kb + cq],     ah[1], al[1]);
            split_tf32(Qs[(wq + r)     * AQ_STR + kb + cq + 4], ah[2], al[2]);
            split_tf32(Qs[(wq + r + 8) * AQ_STR + kb + cq + 4], ah[3], al[3]);
            #pragma unroll
            for (int nt = 0; nt < 2; nt++) {
                uint32_t bh2[2], bl2[2];
                split_tf32(Ks[(wn + nt * 8 + r) * AQ_STR + kb + cq],     bh2[0], bl2[0]);
                split_tf32(Ks[(wn + nt * 8 + r) * AQ_STR + kb + cq + 4], bh2[1], bl2[1]);
                mma8(acc[nt], ah, bh2);
                mma8(acc[nt], ah, bl2);
                mma8(acc[nt], al, bh2);
            }
        }

        int jb = q0 - 256 + c * 64;
        #pragma unroll
        for (int nt = 0; nt < 2; nt++) {
            int jl = wn + nt * 8 + 2 * cq;
            #pragma unroll
            for (int u = 0; u < 2; u++) {
                int qq = wq + r + u * 8;
                int qi = q0 + qq;
                #pragma unroll
                for (int w2 = 0; w2 < 2; w2++) {
                    int jj = jb + jl + w2;
                    bool valid = (jj >= 0) && (jj <= qi) && (qi - jj < WIN);
                    sc[qq * ASC_STR + c * 64 + jl + w2] =
                        valid ? acc[nt][u * 2 + w2] * scale : -1e30f;
                }
            }
        }
        __syncthreads();
    }

    // -------- Phase B: softmax, 8 threads per row -------------------------
    {
        int qq = tid >> 3, g = tid & 7;
        float* row = sc + qq * ASC_STR;
        float mx = -1e30f;
        for (int s = g; s < 320; s += 8) mx = fmaxf(mx, row[s]);
        mx = fmaxf(mx, __shfl_xor_sync(0xffffffffu, mx, 1));
        mx = fmaxf(mx, __shfl_xor_sync(0xffffffffu, mx, 2));
        mx = fmaxf(mx, __shfl_xor_sync(0xffffffffu, mx, 4));
        float sum = 0.f;
        for (int s = g; s < 320; s += 8) {
            float e = expf(row[s] - mx);
            row[s] = e;
            sum += e;
        }
        sum += __shfl_xor_sync(0xffffffffu, sum, 1);
        sum += __shfl_xor_sync(0xffffffffu, sum, 2);
        sum += __shfl_xor_sync(0xffffffffu, sum, 4);
        float inv = 1.f / sum;
        for (int s = g; s < 320; s += 8) row[s] *= inv;
    }
    __syncthreads();

    // -------- Phase C: write full attn rows (zeros + probs) ---------------
    {
        int c4 = tid & 255;
        int half = tid >> 8;
        for (int it = 0; it < 32; it++) {
            int qq = it * 2 + half;
            int qi = q0 + qq;
            const float* src = sc + qq * ASC_STR;
            float rr[4];
            #pragma unroll
            for (int u = 0; u < 4; u++) {
                int j = c4 * 4 + u;
                bool in = (j <= qi) && (qi - j < WIN);
                rr[u] = in ? src[j - q0 + 256] : 0.f;
            }
            ((float4*)(attn_out + ((size_t)bh * SS + qi) * SS))[c4] =
                make_float4(rr[0], rr[1], rr[2], rr[3]);
        }
    }
    __syncthreads();

    // -------- Phase D: out = P @ V, double-buffered V ----------------------
    // V pre-rounded to tf32 => raw bits; probs converted once per fragment.
    float oacc[2][4];
    #pragma unroll
    for (int i = 0; i < 2; i++)
        #pragma unroll
        for (int j = 0; j < 4; j++) oacc[i][j] = 0.f;

    loadKV(vbase, KVb[0], q0 - 256);
    asm volatile("cp.async.commit_group;\n" ::);
    for (int c = 0; c < 5; c++) {
        if (c < 4) {
            loadKV(vbase, KVb[(c + 1) & 1], q0 - 256 + (c + 1) * 64);
            asm volatile("cp.async.commit_group;\n" ::);
            asm volatile("cp.async.wait_group 1;\n" ::);
        } else {
            asm volatile("cp.async.wait_group 0;\n" ::);
        }
        __syncthreads();
        const float* Vs = KVb[c & 1];   // [kk][d]

        #pragma unroll
        for (int kb = 0; kb < 64; kb += 8) {
            uint32_t ah[4];
            ah[0] = f2tf32(sc[(wq + r)     * ASC_STR + c * 64 + kb + cq]);
            ah[1] = f2tf32(sc[(wq + r + 8) * ASC_STR + c * 64 + kb + cq]);
            ah[2] = f2tf32(sc[(wq + r)     * ASC_STR + c * 64 + kb + cq + 4]);
            ah[3] = f2tf32(sc[(wq + r + 8) * ASC_STR + c * 64 + kb + cq + 4]);
            #pragma unroll
            for (int nt = 0; nt < 2; nt++) {
                uint32_t bb[2];
                bb[0] = __float_as_uint(Vs[(kb + cq)     * AQ_STR + wn + nt * 8 + r]);
                bb[1] = __float_as_uint(Vs[(kb + cq + 4) * AQ_STR + wn + nt * 8 + r]);
                mma8(oacc[nt], ah, bb);
            }
        }
        __syncthreads();
    }

    #pragma unroll
    for (int nt = 0; nt < 2; nt++) {
        int d0 = wn + nt * 8 + 2 * cq;
        size_t b0 = ((size_t)(b * SS + q0 + wq + r))     * DD + h * HDIM + d0;
        size_t b1 = ((size_t)(b * SS + q0 + wq + r + 8)) * DD + h * HDIM + d0;
        *(float2*)(ao + b0) = make_float2(rnd_tf32(oacc[nt][0]), rnd_tf32(oacc[nt][1]));
        *(float2*)(ao + b1) = make_float2(rnd_tf32(oacc[nt][2]), rnd_tf32(oacc[nt][3]));
    }
}

// ---------------- launcher -------------------------------------------------
extern "C" void kernel_launch(void* const* d_in, const int* in_sizes, int n_in,
                              void* d_out, int out_size) {
    const float* x   = (const float*)d_in[0];
    const float* wq  = (const float*)d_in[1];
    const float* bq  = (const float*)d_in[2];
    const float* wk  = (const float*)d_in[3];
    const float* bk  = (const float*)d_in[4];
    const float* wv  = (const float*)d_in[5];
    const float* bv  = (const float*)d_in[6];
    const float* wo  = (const float*)d_in[7];
    const float* bo  = (const float*)d_in[8];
    const float* anw = (const float*)d_in[9];
    const float* fnw = (const float*)d_in[10];
    const float* gw  = (const float*)d_in[11];
    const float* uw  = (const float*)d_in[12];
    const float* dw  = (const float*)d_in[13];

    float* outx = (float*)d_out;                       // [B,S,D]
    float* outa = outx + (size_t)MR * DD;              // [B,H,S,S]

    float *p_h, *p_q, *p_k, *p_v, *p_ao, *p_x1, *p_h2, *p_gate, *p_up, *p_wr;
    cudaGetSymbolAddress((void**)&p_h,    g_h);
    cudaGetSymbolAddress((void**)&p_q,    g_q);
    cudaGetSymbolAddress((void**)&p_k,    g_k);
    cudaGetSymbolAddress((void**)&p_v,    g_v);
    cudaGetSymbolAddress((void**)&p_ao,   g_ao);
    cudaGetSymbolAddress((void**)&p_x1,   g_x1);
    cudaGetSymbolAddress((void**)&p_h2,   g_h2);
    cudaGetSymbolAddress((void**)&p_gate, g_gate);
    cudaGetSymbolAddress((void**)&p_up,   g_up);
    cudaGetSymbolAddress((void**)&p_wr,   g_wr);

    const size_t MB1 = 1024 * 1024;
    float* rwq = p_wr;            float* rwk = p_wr + 1 * MB1;
    float* rwv = p_wr + 2 * MB1;  float* rwo = p_wr + 3 * MB1;
    float* rgw = p_wr + 4 * MB1;  float* ruw = p_wr + 8 * MB1;
    float* rdw = p_wr + 12 * MB1;

    cudaFuncSetAttribute(attn_kernel,
                         cudaFuncAttributeMaxDynamicSharedMemorySize, ATTN_SMEM);
    cudaFuncSetAttribute(gemm_tf32<true, false>,
                         cudaFuncAttributeMaxDynamicSharedMemorySize, GEMM_SMEM);
    cudaFuncSetAttribute(gemm_tf32<true, true>,
                         cudaFuncAttributeMaxDynamicSharedMemorySize, GEMM_SMEM);
    cudaFuncSetAttribute(gemm_tf32<false, false>,
                         cudaFuncAttributeMaxDynamicSharedMemorySize, GEMM_SMEM);
    cudaFuncSetAttribute(gemm_tf32<false, true>,
                         cudaFuncAttributeMaxDynamicSharedMemorySize, GEMM_SMEM);

    // 0) pre-round all weights to tf32 (rna) so HW truncation is exact
    round_tf32_kernel<<<1024, 256>>>((const float4*)wq, (float4*)rwq, 262144);
    round_tf32_kernel<<<1024, 256>>>((const float4*)wk, (float4*)rwk, 262144);
    round_tf32_kernel<<<1024, 256>>>((const float4*)wv, (float4*)rwv, 262144);
    round_tf32_kernel<<<1024, 256>>>((const float4*)wo, (float4*)rwo, 262144);
    round_tf32_kernel<<<4096, 256>>>((const float4*)gw, (float4*)rgw, 1048576);
    round_tf32_kernel<<<4096, 256>>>((const float4*)uw, (float4*)ruw, 1048576);
    round_tf32_kernel<<<4096, 256>>>((const float4*)dw, (float4*)rdw, 1048576);

    // 1) attn rmsnorm (output tf32-rounded)
    rmsnorm_kernel<<<MR, 256>>>(x, anw, p_h);

    // 2) QKV — one z=3 launch (bits-direct tf32)
    {
        GemmArgs a;
        a.w[0] = rwq; a.w[1] = rwk; a.w[2] = rwv;
        a.b[0] = bq;  a.b[1] = bk;  a.b[2] = bv;
        a.c[0] = p_q; a.c[1] = p_k; a.c[2] = p_v;
        gemm_tf32<true, false><<<dim3(DD/128, MR/128, 3), 256, GEMM_SMEM>>>(
            p_h, a, nullptr, MR, DD, DD);
    }
    // 3) RoPE (q,k stay fp32 — phase A uses precise splits)
    rope_kernel<<<(2 * MR * 512) / 256, 256>>>(p_q, p_k);
    // 3b) round V to tf32 in place (phase D feeds raw bits)
    round_tf32_kernel<<<2048, 256>>>((const float4*)p_v, (float4*)p_v, 524288);
    // 4) attention (probs -> outa, context -> g_ao)
    attn_kernel<<<dim3(SS / 64, BB * HH), 512, ATTN_SMEM>>>(p_q, p_k, p_v, p_ao, outa);
    // 5) O proj + bias + residual
    {
        GemmArgs a;
        a.w[0] = rwo; a.b[0] = bo; a.c[0] = p_x1;
        a.w[1] = a.w[2] = nullptr; a.b[1] = a.b[2] = nullptr; a.c[1] = a.c[2] = nullptr;
        gemm_tf32<true, true><<<dim3(DD/128, MR/128, 1), 256, GEMM_SMEM>>>(
            p_ao, a, x, MR, DD, DD);
    }
    // 6) ffn rmsnorm (tf32-rounded output)
    rmsnorm_kernel<<<MR, 256>>>(p_x1, fnw, p_h2);
    // 7) gate + up in one z=2 launch
    {
        GemmArgs a;
        a.w[0] = rgw; a.w[1] = ruw; a.w[2] = nullptr;
        a.b[0] = a.b[1] = a.b[2] = nullptr;
        a.c[0] = p_gate; a.c[1] = p_up; a.c[2] = nullptr;
        gemm_tf32<false, false><<<dim3(FF/128, MR/128, 2), 256, GEMM_SMEM>>>(
            p_h2, a, nullptr, MR, FF, DD);
    }
    // 8) act = silu(gate) * up  (in place into up, tf32-rounded)
    silu_mul_kernel<<<(MR * FF / 4) / 256, 256>>>(p_gate, p_up);
    // 9) down + residual -> final x
    {
        GemmArgs a;
        a.w[0] = rdw; a.b[0] = nullptr; a.c[0] = outx;
        a.w[1] = a.w[2] = nullptr; a.b[1] = a.b[2] = nullptr; a.c[1] = a.c[2] = nullptr;
        gemm_tf32<false, true><<<dim3(DD/128, MR/128, 1), 256, GEMM_SMEM>>>(
            p_up, a, p_x1, MR, DD, FF);
    }
}

// round 6
// speedup vs baseline: 4.8816x; 1.5303x over previous
#include <cuda_runtime.h>
#include <cuda_fp16.h>
#include <cstdint>

// Problem constants
#define BB   2
#define SS   1024
#define DD   1024
#define HH   16
#define HDIM 64
#define WIN  256
#define FF   4096
#define MR   (BB*SS)   // 2048 rows

// ---------------- scratch (device globals; no allocation allowed) ----------
__device__ float  g_q   [MR*DD];
__device__ float  g_k   [MR*DD];
__device__ float  g_v   [MR*DD];
__device__ float  g_x1  [MR*DD];
__device__ float  g_gate[MR*FF];
__device__ float  g_up  [MR*FF];
__device__ __half g_hh  [MR*DD];    // rmsnorm1 out (fp16, GEMM A)
__device__ __half g_h2h [MR*DD];    // rmsnorm2 out
__device__ __half g_aoh [MR*DD];    // attn context out
__device__ __half g_acth[MR*FF];    // silu(gate)*up
__device__ __half g_wh  [16*1024*1024];  // fp16 weights: wq wk wv wo gw uw dw

// ---------------- common PTX helpers ---------------------------------------
__device__ __forceinline__ void cp16(void* smem_dst, const void* gsrc) {
    uint32_t s = (uint32_t)__cvta_generic_to_shared(smem_dst);
    asm volatile("cp.async.cg.shared.global [%0], [%1], 16;\n" :: "r"(s), "l"(gsrc));
}
__device__ __forceinline__ uint32_t f2tf32(float x) {
    uint32_t u;
    asm("cvt.rna.tf32.f32 %0, %1;" : "=r"(u) : "f"(x));
    return u;
}
__device__ __forceinline__ float rnd_tf32(float x) {
    return __uint_as_float(f2tf32(x));
}
__device__ __forceinline__ void split_tf32(float x, uint32_t& hi, uint32_t& lo) {
    hi = f2tf32(x);
    float rem = x - __uint_as_float(hi);
    lo = f2tf32(rem);
}
__device__ __forceinline__ void mma8(float* d, const uint32_t* a, const uint32_t* b) {
    asm volatile(
        "mma.sync.aligned.m16n8k8.row.col.f32.tf32.tf32.f32 "
        "{%0,%1,%2,%3}, {%4,%5,%6,%7}, {%8,%9}, {%0,%1,%2,%3};\n"
        : "+f"(d[0]), "+f"(d[1]), "+f"(d[2]), "+f"(d[3])
        : "r"(a[0]), "r"(a[1]), "r"(a[2]), "r"(a[3]), "r"(b[0]), "r"(b[1]));
}
__device__ __forceinline__ void mma16h(float* d, const uint32_t* a, const uint32_t* b) {
    asm volatile(
        "mma.sync.aligned.m16n8k16.row.col.f32.f16.f16.f32 "
        "{%0,%1,%2,%3}, {%4,%5,%6,%7}, {%8,%9}, {%0,%1,%2,%3};\n"
        : "+f"(d[0]), "+f"(d[1]), "+f"(d[2]), "+f"(d[3])
        : "r"(a[0]), "r"(a[1]), "r"(a[2]), "r"(a[3]), "r"(b[0]), "r"(b[1]));
}
__device__ __forceinline__ void ldmx4(uint32_t* r, uint32_t addr) {
    asm volatile("ldmatrix.sync.aligned.m8n8.x4.shared.b16 {%0,%1,%2,%3}, [%4];"
                 : "=r"(r[0]), "=r"(r[1]), "=r"(r[2]), "=r"(r[3]) : "r"(addr));
}
__device__ __forceinline__ void ldmx2(uint32_t* r, uint32_t addr) {
    asm volatile("ldmatrix.sync.aligned.m8n8.x2.shared.b16 {%0,%1}, [%2];"
                 : "=r"(r[0]), "=r"(r[1]) : "r"(addr));
}
__device__ __forceinline__ uint32_t smem_u32(const void* p) {
    return (uint32_t)__cvta_generic_to_shared(p);
}

// ---------------- elementwise kernels ---------------------------------------
struct WSet {
    const float4* src[7];
    __half* dst[7];
    int n4[7];
};

__global__ void round_weights_kernel(WSet ws) {
    int reg = blockIdx.y;
    int i = blockIdx.x * 256 + threadIdx.x;
    if (i < ws.n4[reg]) {
        float4 v = ws.src[reg][i];
        __half2 h01 = __floats2half2_rn(v.x, v.y);
        __half2 h23 = __floats2half2_rn(v.z, v.w);
        uint2 o;
        o.x = *(uint32_t*)&h01;
        o.y = *(uint32_t*)&h23;
        ((uint2*)ws.dst[reg])[i] = o;
    }
}

__global__ void round_tf32_kernel(const float4* __restrict__ in,
                                  float4* __restrict__ out, int n4) {
    int i = blockIdx.x * 256 + threadIdx.x;
    if (i < n4) {
        float4 v = in[i];
        v.x = rnd_tf32(v.x); v.y = rnd_tf32(v.y);
        v.z = rnd_tf32(v.z); v.w = rnd_tf32(v.w);
        out[i] = v;
    }
}

// RMSNorm: fp32 in, fp16 out (feeds GEMM A side)
__global__ void rmsnorm_kernel(const float* __restrict__ x,
                               const float* __restrict__ w,
                               __half* __restrict__ out) {
    int row = blockIdx.x;
    int tid = threadIdx.x;
    const float4 xv = ((const float4*)(x + (size_t)row * DD))[tid];
    float ss = xv.x*xv.x + xv.y*xv.y + xv.z*xv.z + xv.w*xv.w;
    #pragma unroll
    for (int o = 16; o; o >>= 1) ss += __shfl_xor_sync(0xffffffffu, ss, o);
    __shared__ float red[8];
    if ((tid & 31) == 0) red[tid >> 5] = ss;
    __syncthreads();
    if (tid < 32) {
        float v = (tid < 8) ? red[tid] : 0.f;
        #pragma unroll
        for (int o = 4; o; o >>= 1) v += __shfl_xor_sync(0xffffffffu, v, o);
        if (tid == 0) red[0] = v;
    }
    __syncthreads();
    float inv = rsqrtf(red[0] * (1.0f / DD) + 1e-6f);
    float4 wv = ((const float4*)w)[tid];
    __half2 h01 = __floats2half2_rn(xv.x * inv * wv.x, xv.y * inv * wv.y);
    __half2 h23 = __floats2half2_rn(xv.z * inv * wv.z, xv.w * inv * wv.w);
    uint2 o;
    o.x = *(uint32_t*)&h01;
    o.y = *(uint32_t*)&h23;
    ((uint2*)(out + (size_t)row * DD))[tid] = o;
}

__global__ void rope_kernel(float* __restrict__ q, float* __restrict__ k) {
    int t = blockIdx.x * blockDim.x + threadIdx.x;
    int total = MR * 512;
    float* p = (t < total) ? q : k;
    int u = (t < total) ? t : (t - total);
    int m  = u >> 9;
    int pr = u & 511;
    int hh = pr >> 5;
    int i  = pr & 31;
    int s  = m & (SS - 1);
    float inv = expf(-(float)i * 0.28782313662425576f);   // ln(10000)/32
    float ang = (float)s * inv;
    float c = cosf(ang), sn = sinf(ang);
    size_t base = (size_t)m * DD + hh * HDIM + i;
    float x1 = p[base];
    float x2 = p[base + 32];
    p[base]      = x1 * c - x2 * sn;
    p[base + 32] = x2 * c + x1 * sn;
}

// silu(gate) * up -> fp16 act
__global__ void silu_mul_kernel(const float* __restrict__ g,
                                const float* __restrict__ u,
                                __half* __restrict__ act) {
    int i = blockIdx.x * blockDim.x + threadIdx.x;
    float4 gv = ((const float4*)g)[i];
    float4 uv = ((const float4*)u)[i];
    float a0 = uv.x * gv.x / (1.f + expf(-gv.x));
    float a1 = uv.y * gv.y / (1.f + expf(-gv.y));
    float a2 = uv.z * gv.z / (1.f + expf(-gv.z));
    float a3 = uv.w * gv.w / (1.f + expf(-gv.w));
    __half2 h01 = __floats2half2_rn(a0, a1);
    __half2 h23 = __floats2half2_rn(a2, a3);
    uint2 o;
    o.x = *(uint32_t*)&h01;
    o.y = *(uint32_t*)&h23;
    ((uint2*)act)[i] = o;
}

// ---------------- fp16 tensor-core GEMM, 3-stage cp.async ------------------
// C[M,N](fp32) = A[M,K](fp16) @ W[N,K](fp16)^T (+bias, +res).
// 128x128x32 tile, 256 threads, 8 warps (2x4), warp tile 64x32,
// mma.m16n8k16.f16 with f32 accum, ldmatrix fragment loads.

struct GemmArgs {
    const __half* w[3];
    const float* b[3];
    float* c[3];
};

#define HS_STR 40                         // halfs per smem row (80 B, pad 8)
#define HS_TILE (128 * HS_STR)            // halfs per stage per matrix
#define GEMM_SMEM (6 * HS_TILE * 2)       // 3 stages x (A+B) bytes = 61440

template<bool HAS_BIAS, bool HAS_RES>
__global__ void __launch_bounds__(256)
gemm_f16(const __half* __restrict__ A, GemmArgs args,
         const float* __restrict__ res, int M, int N, int K) {
    const __half* __restrict__ W = args.w[blockIdx.z];
    const float* __restrict__ bias = args.b[blockIdx.z];
    float* __restrict__ C = args.c[blockIdx.z];

    extern __shared__ __half smh[];
    __half* Asb = smh;                    // 3 stages of [128][40]
    __half* Bsb = smh + 3 * HS_TILE;

    int bm = blockIdx.y, bn = blockIdx.x;
    int tid = threadIdx.x;
    int lane = tid & 31, warp = tid >> 5;
    int wm = (warp >> 2) * 64;
    int wn = (warp & 3) * 32;
    int r = lane >> 2, cq = lane & 3;

    float acc[4][4][4];
    #pragma unroll
    for (int i = 0; i < 4; i++)
        #pragma unroll
        for (int j = 0; j < 4; j++)
            #pragma unroll
            for (int t = 0; t < 4; t++) acc[i][j][t] = 0.f;

    const __half* Abase = A + (size_t)(bm * 128) * K;
    const __half* Wbase = W + (size_t)(bn * 128) * K;
    int lr = tid >> 2;            // 0..63  (row / 2 pass)
    int lc = (tid & 3) * 8;       // half offset within 32-k tile

    auto load_tile = [&](int st, int k0) {
        __half* As = Asb + st * HS_TILE;
        __half* Bs = Bsb + st * HS_TILE;
        #pragma unroll
        for (int i = 0; i < 2; i++) {
            int row = lr + 64 * i;
            cp16(&As[row * HS_STR + lc], Abase + (size_t)row * K + k0 + lc);
            cp16(&Bs[row * HS_STR + lc], Wbase + (size_t)row * K + k0 + lc);
        }
    };

    int nk = K >> 5;
    load_tile(0, 0);
    asm volatile("cp.async.commit_group;\n" ::);
    load_tile(1, 32);
    asm volatile("cp.async.commit_group;\n" ::);

    // ldmatrix lane addressing
    int a_row = lane & 15, a_col = (lane >> 4) * 8;
    int b_row = lane & 7,  b_col = ((lane >> 3) & 1) * 8;

    int s = 0;
    for (int kt = 0; kt < nk; kt++) {
        if (kt + 1 < nk) {
            asm volatile("cp.async.wait_group 1;\n" ::);
        } else {
            asm volatile("cp.async.wait_group 0;\n" ::);
        }
        __syncthreads();
        if (kt + 2 < nk) {
            int s2 = s + 2; if (s2 >= 3) s2 -= 3;
            load_tile(s2, (kt + 2) * 32);
            asm volatile("cp.async.commit_group;\n" ::);
        }

        const __half* As = Asb + s * HS_TILE;
        const __half* Bs = Bsb + s * HS_TILE;
        #pragma unroll
        for (int ks = 0; ks < 2; ks++) {
            int kb = ks * 16;
            uint32_t af[4][4], bf[4][2];
            #pragma unroll
            for (int mt = 0; mt < 4; mt++)
                ldmx4(af[mt], smem_u32(&As[(wm + mt * 16 + a_row) * HS_STR + kb + a_col]));
            #pragma unroll
            for (int nt = 0; nt < 4; nt++)
                ldmx2(bf[nt], smem_u32(&Bs[(wn + nt * 8 + b_row) * HS_STR + kb + b_col]));
            #pragma unroll
            for (int mt = 0; mt < 4; mt++)
                #pragma unroll
                for (int nt = 0; nt < 4; nt++)
                    mma16h(acc[mt][nt], af[mt], bf[nt]);
        }
        s = s + 1; if (s >= 3) s -= 3;
    }

    // epilogue (fp32 out)
    #pragma unroll
    for (int mt = 0; mt < 4; mt++) {
        int row0 = bm * 128 + wm + mt * 16 + r;
        #pragma unroll
        for (int nt = 0; nt < 4; nt++) {
            int col = bn * 128 + wn + nt * 8 + 2 * cq;
            float2 v0 = make_float2(acc[mt][nt][0], acc[mt][nt][1]);
            float2 v1 = make_float2(acc[mt][nt][2], acc[mt][nt][3]);
            if (HAS_BIAS) {
                float2 bb = *(const float2*)(bias + col);
                v0.x += bb.x; v0.y += bb.y; v1.x += bb.x; v1.y += bb.y;
            }
            size_t i0 = (size_t)row0 * N + col;
            size_t i1 = i0 + (size_t)8 * N;
            if (HAS_RES) {
                float2 r0 = *(const float2*)(res + i0);
                float2 r1 = *(const float2*)(res + i1);
                v0.x += r0.x; v0.y += r0.y; v1.x += r1.x; v1.y += r1.y;
            }
            *(float2*)(C + i0) = v0;
            *(float2*)(C + i1) = v1;
        }
    }
}

// ---------------- sliding-window attention (512 threads) -------------------
#define AQ_STR 68
#define ASC_STR 321
#define A_KV0 (64 * AQ_STR)
#define A_KV1 (2 * 64 * AQ_STR)
#define A_SC  (3 * 64 * AQ_STR)
#define ATTN_SMEM ((3 * 64 * AQ_STR + 64 * ASC_STR) * 4)

__global__ void __launch_bounds__(512)
attn_kernel(const float* __restrict__ q, const float* __restrict__ k,
            const float* __restrict__ v, __half* __restrict__ ao,
            float* __restrict__ attn_out) {
    extern __shared__ float sm[];
    float* Qs = sm;
    float* KVb[2] = { sm + A_KV0, sm + A_KV1 };
    float* sc = sm + A_SC;

    int q0 = blockIdx.x * 64;
    int bh = blockIdx.y;
    int b  = bh >> 4, h = bh & 15;
    int tid = threadIdx.x;
    int lane = tid & 31, warp = tid >> 5;
    int wq = (warp & 3) * 16;            // query tile
    int wn = (warp >> 2) * 16;           // key/dim tile
    int r = lane >> 2, cq = lane & 3;
    const float scale = 0.125f;

    const float* kbase = k + (size_t)(b * SS) * DD + h * HDIM;
    const float* vbase = v + (size_t)(b * SS) * DD + h * HDIM;

    for (int t = tid; t < 64 * 64; t += 512) {
        int qq = t >> 6, d = t & 63;
        Qs[qq * AQ_STR + d] = q[((size_t)(b * SS + q0 + qq)) * DD + h * HDIM + d];
    }

    auto loadKV = [&](const float* base, float* dst, int jb) {
        #pragma unroll
        for (int i = 0; i < 2; i++) {
            int ch = tid + 512 * i;
            int kk = ch >> 4, dq = (ch & 15) * 4;
            int j = jb + kk;
            if (j >= 0) cp16(&dst[kk * AQ_STR + dq], base + (size_t)j * DD + dq);
            else *(float4*)&dst[kk * AQ_STR + dq] = make_float4(0.f, 0.f, 0.f, 0.f);
        }
    };

    // -------- Phase A: scores (precise 3xTF32), double-buffered K ---------
    loadKV(kbase, KVb[0], q0 - 256);
    asm volatile("cp.async.commit_group;\n" ::);
    for (int c = 0; c < 5; c++) {
        if (c < 4) {
            loadKV(kbase, KVb[(c + 1) & 1], q0 - 256 + (c + 1) * 64);
            asm volatile("cp.async.commit_group;\n" ::);
            asm volatile("cp.async.wait_group 1;\n" ::);
        } else {
            asm volatile("cp.async.wait_group 0;\n" ::);
        }
        __syncthreads();
        const float* Ks = KVb[c & 1];

        float acc[2][4];
        #pragma unroll
        for (int i = 0; i < 2; i++)
            #pragma unroll
            for (int j = 0; j < 4; j++) acc[i][j] = 0.f;

        #pragma unroll
        for (int kb = 0; kb < 64; kb += 8) {
            uint32_t ah[4], al[4];
            split_tf32(Qs[(wq + r)     * AQ_STR + kb + cq],     ah[0], al[0]);
            split_tf32(Qs[(wq + r + 8) * AQ_STR + kb + cq],     ah[1], al[1]);
            split_tf32(Qs[(wq + r)     * AQ_STR + kb + cq + 4], ah[2], al[2]);
            split_tf32(Qs[(wq + r + 8) * AQ_STR + kb + cq + 4], ah[3], al[3]);
            #pragma unroll
            for (int nt = 0; nt < 2; nt++) {
                uint32_t bh2[2], bl2[2];
                split_tf32(Ks[(wn + nt * 8 + r) * AQ_STR + kb + cq],     bh2[0], bl2[0]);
                split_tf32(Ks[(wn + nt * 8 + r) * AQ_STR + kb + cq + 4], bh2[1], bl2[1]);
                mma8(acc[nt], ah, bh2);
                mma8(acc[nt], ah, bl2);
                mma8(acc[nt], al, bh2);
            }
        }

        int jb = q0 - 256 + c * 64;
        #pragma unroll
        for (int nt = 0; nt < 2; nt++) {
            int jl = wn + nt * 8 + 2 * cq;
            #pragma unroll
            for (int u = 0; u < 2; u++) {
                int qq = wq + r + u * 8;
                int qi = q0 + qq;
                #pragma unroll
                for (int w2 = 0; w2 < 2; w2++) {
                    int jj = jb + jl + w2;
                    bool valid = (jj >= 0) && (jj <= qi) && (qi - jj < WIN);
                    sc[qq * ASC_STR + c * 64 + jl + w2] =
                        valid ? acc[nt][u * 2 + w2] * scale : -1e30f;
                }
            }
        }
        __syncthreads();
    }

    // -------- Phase B: softmax, 8 threads per row -------------------------
    {
        int qq = tid >> 3, g = tid & 7;
        float* row = sc + qq * ASC_STR;
        float mx = -1e30f;
        for (int s = g; s < 320; s += 8) mx = fmaxf(mx, row[s]);
        mx = fmaxf(mx, __shfl_xor_sync(0xffffffffu, mx, 1));
        mx = fmaxf(mx, __shfl_xor_sync(0xffffffffu, mx, 2));
        mx = fmaxf(mx, __shfl_xor_sync(0xffffffffu, mx, 4));
        float sum = 0.f;
        for (int s = g; s < 320; s += 8) {
            float e = expf(row[s] - mx);
            row[s] = e;
            sum += e;
        }
        sum += __shfl_xor_sync(0xffffffffu, sum, 1);
        sum += __shfl_xor_sync(0xffffffffu, sum, 2);
        sum += __shfl_xor_sync(0xffffffffu, sum, 4);
        float inv = 1.f / sum;
        for (int s = g; s < 320; s += 8) row[s] *= inv;
    }
    __syncthreads();

    // -------- Phase C: write full attn rows (zeros + probs) ---------------
    {
        int c4 = tid & 255;
        int half = tid >> 8;
        for (int it = 0; it < 32; it++) {
            int qq = it * 2 + half;
            int qi = q0 + qq;
            const float* src = sc + qq * ASC_STR;
            float rr[4];
            #pragma unroll
            for (int u = 0; u < 4; u++) {
                int j = c4 * 4 + u;
                bool in = (j <= qi) && (qi - j < WIN);
                rr[u] = in ? src[j - q0 + 256] : 0.f;
            }
            ((float4*)(attn_out + ((size_t)bh * SS + qi) * SS))[c4] =
                make_float4(rr[0], rr[1], rr[2], rr[3]);
        }
    }
    __syncthreads();

    // -------- Phase D: out = P @ V, double-buffered V ----------------------
    float oacc[2][4];
    #pragma unroll
    for (int i = 0; i < 2; i++)
        #pragma unroll
        for (int j = 0; j < 4; j++) oacc[i][j] = 0.f;

    loadKV(vbase, KVb[0], q0 - 256);
    asm volatile("cp.async.commit_group;\n" ::);
    for (int c = 0; c < 5; c++) {
        if (c < 4) {
            loadKV(vbase, KVb[(c + 1) & 1], q0 - 256 + (c + 1) * 64);
            asm volatile("cp.async.commit_group;\n" ::);
            asm volatile("cp.async.wait_group 1;\n" ::);
        } else {
            asm volatile("cp.async.wait_group 0;\n" ::);
        }
        __syncthreads();
        const float* Vs = KVb[c & 1];   // [kk][d]

        #pragma unroll
        for (int kb = 0; kb < 64; kb += 8) {
            uint32_t ah[4];
            ah[0] = f2tf32(sc[(wq + r)     * ASC_STR + c * 64 + kb + cq]);
            ah[1] = f2tf32(sc[(wq + r + 8) * ASC_STR + c * 64 + kb + cq]);
            ah[2] = f2tf32(sc[(wq + r)     * ASC_STR + c * 64 + kb + cq + 4]);
            ah[3] = f2tf32(sc[(wq + r + 8) * ASC_STR + c * 64 + kb + cq + 4]);
            #pragma unroll
            for (int nt = 0; nt < 2; nt++) {
                uint32_t bb[2];
                bb[0] = __float_as_uint(Vs[(kb + cq)     * AQ_STR + wn + nt * 8 + r]);
                bb[1] = __float_as_uint(Vs[(kb + cq + 4) * AQ_STR + wn + nt * 8 + r]);
                mma8(oacc[nt], ah, bb);
            }
        }
        __syncthreads();
    }

    #pragma unroll
    for (int nt = 0; nt < 2; nt++) {
        int d0 = wn + nt * 8 + 2 * cq;
        size_t b0 = ((size_t)(b * SS + q0 + wq + r))     * DD + h * HDIM + d0;
        size_t b1 = ((size_t)(b * SS + q0 + wq + r + 8)) * DD + h * HDIM + d0;
        __half2 h0 = __floats2half2_rn(oacc[nt][0], oacc[nt][1]);
        __half2 h1 = __floats2half2_rn(oacc[nt][2], oacc[nt][3]);
        *(__half2*)(ao + b0) = h0;
        *(__half2*)(ao + b1) = h1;
    }
}

// ---------------- launcher -------------------------------------------------
extern "C" void kernel_launch(void* const* d_in, const int* in_sizes, int n_in,
                              void* d_out, int out_size) {
    const float* x   = (const float*)d_in[0];
    const float* wq  = (const float*)d_in[1];
    const float* bq  = (const float*)d_in[2];
    const float* wk  = (const float*)d_in[3];
    const float* bk  = (const float*)d_in[4];
    const float* wv  = (const float*)d_in[5];
    const float* bv  = (const float*)d_in[6];
    const float* wo  = (const float*)d_in[7];
    const float* bo  = (const float*)d_in[8];
    const float* anw = (const float*)d_in[9];
    const float* fnw = (const float*)d_in[10];
    const float* gw  = (const float*)d_in[11];
    const float* uw  = (const float*)d_in[12];
    const float* dw  = (const float*)d_in[13];

    float* outx = (float*)d_out;                       // [B,S,D]
    float* outa = outx + (size_t)MR * DD;              // [B,H,S,S]

    float *p_q, *p_k, *p_v, *p_x1, *p_gate, *p_up;
    __half *p_hh, *p_h2h, *p_aoh, *p_acth, *p_wh;
    cudaGetSymbolAddress((void**)&p_q,    g_q);
    cudaGetSymbolAddress((void**)&p_k,    g_k);
    cudaGetSymbolAddress((void**)&p_v,    g_v);
    cudaGetSymbolAddress((void**)&p_x1,   g_x1);
    cudaGetSymbolAddress((void**)&p_gate, g_gate);
    cudaGetSymbolAddress((void**)&p_up,   g_up);
    cudaGetSymbolAddress((void**)&p_hh,   g_hh);
    cudaGetSymbolAddress((void**)&p_h2h,  g_h2h);
    cudaGetSymbolAddress((void**)&p_aoh,  g_aoh);
    cudaGetSymbolAddress((void**)&p_acth, g_acth);
    cudaGetSymbolAddress((void**)&p_wh,   g_wh);

    const size_t MB1 = 1024 * 1024;
    __half* hwq = p_wh;            __half* hwk = p_wh + 1 * MB1;
    __half* hwv = p_wh + 2 * MB1;  __half* hwo = p_wh + 3 * MB1;
    __half* hgw = p_wh + 4 * MB1;  __half* huw = p_wh + 8 * MB1;
    __half* hdw = p_wh + 12 * MB1;

    cudaFuncSetAttribute(attn_kernel,
                         cudaFuncAttributeMaxDynamicSharedMemorySize, ATTN_SMEM);
    cudaFuncSetAttribute(gemm_f16<true, false>,
                         cudaFuncAttributeMaxDynamicSharedMemorySize, GEMM_SMEM);
    cudaFuncSetAttribute(gemm_f16<true, true>,
                         cudaFuncAttributeMaxDynamicSharedMemorySize, GEMM_SMEM);
    cudaFuncSetAttribute(gemm_f16<false, false>,
                         cudaFuncAttributeMaxDynamicSharedMemorySize, GEMM_SMEM);
    cudaFuncSetAttribute(gemm_f16<false, true>,
                         cudaFuncAttributeMaxDynamicSharedMemorySize, GEMM_SMEM);

    // 0) convert all weights to fp16 in one launch
    {
        WSet ws;
        ws.src[0] = (const float4*)wq; ws.dst[0] = hwq; ws.n4[0] = 262144;
        ws.src[1] = (const float4*)wk; ws.dst[1] = hwk; ws.n4[1] = 262144;
        ws.src[2] = (const float4*)wv; ws.dst[2] = hwv; ws.n4[2] = 262144;
        ws.src[3] = (const float4*)wo; ws.dst[3] = hwo; ws.n4[3] = 262144;
        ws.src[4] = (const float4*)gw; ws.dst[4] = hgw; ws.n4[4] = 1048576;
        ws.src[5] = (const float4*)uw; ws.dst[5] = huw; ws.n4[5] = 1048576;
        ws.src[6] = (const float4*)dw; ws.dst[6] = hdw; ws.n4[6] = 1048576;
        round_weights_kernel<<<dim3(4096, 7), 256>>>(ws);
    }

    // 1) attn rmsnorm -> fp16
    rmsnorm_kernel<<<MR, 256>>>(x, anw, p_hh);

    // 2) QKV — one z=3 fp16 launch
    {
        GemmArgs a;
        a.w[0] = hwq; a.w[1] = hwk; a.w[2] = hwv;
        a.b[0] = bq;  a.b[1] = bk;  a.b[2] = bv;
        a.c[0] = p_q; a.c[1] = p_k; a.c[2] = p_v;
        gemm_f16<true, false><<<dim3(DD/128, MR/128, 3), 256, GEMM_SMEM>>>(
            p_hh, a, nullptr, MR, DD, DD);
    }
    // 3) RoPE (fp32 q/k)
    rope_kernel<<<(2 * MR * 512) / 256, 256>>>(p_q, p_k);
    // 3b) round V to tf32 in place (phase D feeds raw bits)
    round_tf32_kernel<<<2048, 256>>>((const float4*)p_v, (float4*)p_v, 524288);
    // 4) attention (probs -> outa, context -> g_aoh fp16)
    attn_kernel<<<dim3(SS / 64, BB * HH), 512, ATTN_SMEM>>>(p_q, p_k, p_v, p_aoh, outa);
    // 5) O proj + bias + residual
    {
        GemmArgs a;
        a.w[0] = hwo; a.b[0] = bo; a.c[0] = p_x1;
        a.w[1] = a.w[2] = nullptr; a.b[1] = a.b[2] = nullptr; a.c[1] = a.c[2] = nullptr;
        gemm_f16<true, true><<<dim3(DD/128, MR/128, 1), 256, GEMM_SMEM>>>(
            p_aoh, a, x, MR, DD, DD);
    }
    // 6) ffn rmsnorm -> fp16
    rmsnorm_kernel<<<MR, 256>>>(p_x1, fnw, p_h2h);
    // 7) gate + up in one z=2 launch
    {
        GemmArgs a;
        a.w[0] = hgw; a.w[1] = huw; a.w[2] = nullptr;
        a.b[0] = a.b[1] = a.b[2] = nullptr;
        a.c[0] = p_gate; a.c[1] = p_up; a.c[2] = nullptr;
        gemm_f16<false, false><<<dim3(FF/128, MR/128, 2), 256, GEMM_SMEM>>>(
            p_h2h, a, nullptr, MR, FF, DD);
    }
    // 8) act = silu(gate) * up -> fp16
    silu_mul_kernel<<<(MR * FF / 4) / 256, 256>>>(p_gate, p_up, p_acth);
    // 9) down + residual -> final x
    {
        GemmArgs a;
        a.w[0] = hdw; a.b[0] = nullptr; a.c[0] = outx;
        a.w[1] = a.w[2] = nullptr; a.b[1] = a.b[2] = nullptr; a.c[1] = a.c[2] = nullptr;
        gemm_f16<false, true><<<dim3(DD/128, MR/128, 1), 256, GEMM_SMEM>>>(
            p_acth, a, p_x1, MR, DD, FF);
    }
}